// round 2
// baseline (speedup 1.0000x reference)
#include <cuda_runtime.h>
#include <math.h>

#define NIMG 10
#define BB 2
#define LL 5
#define CC 64
#define HH 100
#define WW 352
#define HW 35200
#define KSEL 8800

// ---- scratch (static device globals; no allocation) ----
__device__ float g_confw[NIMG * HW];   // warped confidence (bit-exact vs XLA)
__device__ float g_thr[NIMG];          // per-sample K-th largest conf value
__device__ float g_avg[BB * CC * HW];  // (1/L) * sum_l sparse_l, per batch

// scale constants, computed in double then rounded to f32 (matches Python)
#define S01 ((float)(100.0 / 352.0))
#define S02 ((float)(2.0 / (2.0 * 0.4 * 352.0)))
#define S10 ((float)(352.0 / 100.0))
#define S12 ((float)(2.0 / (2.0 * 0.4 * 100.0)))
#define CXW ((float)(2.0 / 352.0))
#define CYH ((float)(2.0 / 100.0))

// theta = pairwise_t_matrix[b, 0, l, :2, [0,1,3]] * scale  (fast path, non-strict)
__device__ __forceinline__ void get_theta(const float* __restrict__ pt, int b, int l, float th[6]) {
    const float* p = pt + b * (LL * LL * 16) + l * 16;  // i = 0
    th[0] = p[0];
    th[1] = p[1] * S01;
    th[2] = p[3] * S02;
    th[3] = p[4] * S10;
    th[4] = p[5];
    th[5] = p[7] * S12;
}

// ---- XLA f32 tanh (Eigen-style rational approx, uncontracted mul/add) ----
__device__ __forceinline__ float xla_tanh(float x) {
    float cx = fminf(fmaxf(x, -7.90531110763549805f), 7.90531110763549805f);
    float x2 = __fmul_rn(cx, cx);
    float p = -2.76076847742355e-16f;
    p = __fadd_rn(__fmul_rn(p, x2), 2.00018790482477e-13f);
    p = __fadd_rn(__fmul_rn(p, x2), -8.60467152213735e-11f);
    p = __fadd_rn(__fmul_rn(p, x2), 5.12229709037114e-08f);
    p = __fadd_rn(__fmul_rn(p, x2), 1.48572235717979e-05f);
    p = __fadd_rn(__fmul_rn(p, x2), 6.37261928875436e-04f);
    p = __fadd_rn(__fmul_rn(p, x2), 4.89352455891786e-03f);
    float num = __fmul_rn(cx, p);
    float q = 1.19825839466702e-06f;
    q = __fadd_rn(__fmul_rn(q, x2), 1.18534705686654e-04f);
    q = __fadd_rn(__fmul_rn(q, x2), 2.26843463243900e-03f);
    q = __fadd_rn(__fmul_rn(q, x2), 4.89352518554385e-03f);
    float r = __fdiv_rn(num, q);
    return (fabsf(x) < 0.0004f) ? x : r;
}

// XLA LogisticExpander: logistic(x) = 0.5 + 0.5 * tanh(0.5 * x) (0.5 mults exact)
__device__ __forceinline__ float xla_sigmoid(float x) {
    return __fadd_rn(0.5f, __fmul_rn(0.5f, xla_tanh(__fmul_rn(0.5f, x))));
}

// ============================================================
// Kernel 1: warp conf = sigmoid(max(psm over 2 ch)), bilinear.
// STRICT fp32 replication of the XLA op sequence (this feeds the
// discontinuous top-K mask, so it must match bit-for-bit).
// grid (H, N), block W
// ============================================================
__global__ __launch_bounds__(WW) void k_confwarp(const float* __restrict__ psm,
                                                 const float* __restrict__ pt) {
    int h = blockIdx.x, n = blockIdx.y, w = threadIdx.x;
    int b = n / LL, l = n % LL;
    const float* p = pt + b * (LL * LL * 16) + l * 16;
    float th0 = p[0];                    // * 1.0 exact
    float th1 = __fmul_rn(p[1], S01);
    float th2 = __fmul_rn(p[3], S02);
    float th3 = __fmul_rn(p[4], S10);
    float th4 = p[5];                    // * 1.0 exact
    float th5 = __fmul_rn(p[7], S12);

    float gx = __fsub_rn(__fmul_rn(__fadd_rn((float)w, 0.5f), CXW), 1.0f);
    float gy = __fsub_rn(__fmul_rn(__fadd_rn((float)h, 0.5f), CYH), 1.0f);
    float src_x = __fadd_rn(__fadd_rn(__fmul_rn(th0, gx), __fmul_rn(th1, gy)), th2);
    float src_y = __fadd_rn(__fadd_rn(__fmul_rn(th3, gx), __fmul_rn(th4, gy)), th5);
    float px = __fsub_rn(__fmul_rn(__fadd_rn(src_x, 1.0f), 176.0f), 0.5f);
    float py = __fsub_rn(__fmul_rn(__fadd_rn(src_y, 1.0f), 50.0f), 0.5f);
    float x0 = floorf(px), y0 = floorf(py);
    float wx1 = __fsub_rn(px, x0), wx0 = __fsub_rn(1.0f, wx1);
    float wy1 = __fsub_rn(py, y0), wy0 = __fsub_rn(1.0f, wy1);

    const float* base = psm + (size_t)n * 2 * HW;
    float acc = 0.0f;
#pragma unroll
    for (int dy = 0; dy < 2; ++dy) {
#pragma unroll
        for (int dx = 0; dx < 2; ++dx) {
            float yy = dy ? __fadd_rn(y0, 1.0f) : y0;   // exact
            float xx = dx ? __fadd_rn(x0, 1.0f) : x0;   // exact
            if (yy >= 0.0f && yy <= (float)(HH - 1) && xx >= 0.0f && xx <= (float)(WW - 1)) {
                int yi = (int)yy, xi = (int)xx;
                float m = fmaxf(base[yi * WW + xi], base[HW + yi * WW + xi]);
                float s = xla_sigmoid(m);
                float wgt = __fmul_rn(dy ? wy1 : wy0, dx ? wx1 : wx0);
                acc = __fadd_rn(acc, __fmul_rn(s, wgt));
            }
            // invalid term adds exact 0.0f -> identity, skip is bit-equivalent
        }
    }
    g_confw[n * HW + h * WW + w] = acc;
}

// ============================================================
// Kernel 2: exact K-th largest of g_confw[n] via 4x8-bit MSB radix select.
// All values >= 0, so uint bit order == float order. One block per sample.
// ============================================================
__global__ __launch_bounds__(256) void k_select() {
    int n = blockIdx.x;
    const float* v = g_confw + n * HW;
    __shared__ unsigned int hist[256];
    __shared__ unsigned int s_prefix, s_krem;
    if (threadIdx.x == 0) { s_prefix = 0u; s_krem = KSEL; }
    __syncthreads();
    for (int pass = 0; pass < 4; ++pass) {
        int shift = 24 - pass * 8;
        unsigned int pmask = (pass == 0) ? 0u : (0xFFFFFFFFu << (shift + 8));
        for (int i = threadIdx.x; i < 256; i += blockDim.x) hist[i] = 0u;
        __syncthreads();
        unsigned int prefix = s_prefix;
        for (int i = threadIdx.x; i < HW; i += blockDim.x) {
            unsigned int key = __float_as_uint(v[i]);
            if ((key & pmask) == prefix) atomicAdd(&hist[(key >> shift) & 255u], 1u);
        }
        __syncthreads();
        if (threadIdx.x == 0) {
            unsigned int krem = s_krem, c = 0u; int sel = 0;
            for (int bin = 255; bin >= 0; --bin) {
                c += hist[bin];
                if (c >= krem) { sel = bin; krem -= (c - hist[bin]); break; }
            }
            s_prefix = prefix | ((unsigned int)sel << shift);
            s_krem = krem;
        }
        __syncthreads();
    }
    if (threadIdx.x == 0) g_thr[n] = __uint_as_float(s_prefix);
}

// ============================================================
// Kernel 3: for each (b,h,w, 16-channel group): sum over l of
// warp(x_n) * mask_n * (1/L). mask = ego || conf_w >= thr. (continuous path)
// grid (H, 4, B), block W
// ============================================================
__global__ __launch_bounds__(WW) void k_warpacc(const float* __restrict__ x,
                                                const float* __restrict__ pt) {
    int h = blockIdx.x, cg = blockIdx.y, b = blockIdx.z, w = threadIdx.x;
    float acc[16];
#pragma unroll
    for (int i = 0; i < 16; ++i) acc[i] = 0.0f;
    float gx = (w + 0.5f) * (2.0f / WW) - 1.0f;
    float gy = (h + 0.5f) * (2.0f / HH) - 1.0f;
    for (int l = 0; l < LL; ++l) {
        int n = b * LL + l;
        if (l != 0 && g_confw[n * HW + h * WW + w] < g_thr[n]) continue;
        float th[6];
        get_theta(pt, b, l, th);
        float px = (th[0] * gx + th[1] * gy + th[2] + 1.0f) * (WW * 0.5f) - 0.5f;
        float py = (th[3] * gx + th[4] * gy + th[5] + 1.0f) * (HH * 0.5f) - 0.5f;
        float x0 = floorf(px), y0 = floorf(py);
        float wx1 = px - x0, wx0 = 1.0f - wx1;
        float wy1 = py - y0, wy0 = 1.0f - wy1;
        bool vx0 = (x0 >= 0.0f) && (x0 <= (float)(WW - 1));
        bool vx1 = (x0 + 1.0f >= 0.0f) && (x0 + 1.0f <= (float)(WW - 1));
        bool vy0 = (y0 >= 0.0f) && (y0 <= (float)(HH - 1));
        bool vy1 = (y0 + 1.0f >= 0.0f) && (y0 + 1.0f <= (float)(HH - 1));
        int x0i = (int)fminf(fmaxf(x0, 0.0f), (float)(WW - 1));
        int x1i = (int)fminf(fmaxf(x0 + 1.0f, 0.0f), (float)(WW - 1));
        int y0i = (int)fminf(fmaxf(y0, 0.0f), (float)(HH - 1));
        int y1i = (int)fminf(fmaxf(y0 + 1.0f, 0.0f), (float)(HH - 1));
        float m00 = (vy0 && vx0) ? wy0 * wx0 * 0.2f : 0.0f;
        float m01 = (vy0 && vx1) ? wy0 * wx1 * 0.2f : 0.0f;
        float m10 = (vy1 && vx0) ? wy1 * wx0 * 0.2f : 0.0f;
        float m11 = (vy1 && vx1) ? wy1 * wx1 * 0.2f : 0.0f;
        int i00 = y0i * WW + x0i, i01 = y0i * WW + x1i;
        int i10 = y1i * WW + x0i, i11 = y1i * WW + x1i;
        const float* xb = x + (size_t)(n * CC + cg * 16) * HW;
#pragma unroll
        for (int c = 0; c < 16; ++c) {
            const float* xc = xb + c * HW;
            acc[c] += xc[i00] * m00 + xc[i01] * m01 + xc[i10] * m10 + xc[i11] * m11;
        }
    }
    int outbase = ((b * CC + cg * 16) * HH + h) * WW + w;
#pragma unroll
    for (int c = 0; c < 16; ++c) g_avg[outbase + c * HW] = acc[c];
}

// ============================================================
// Kernel 4: 7x7 conv (pad 3) over g_avg[b], 64->64 ch, + bias.
// Tile: 32w x 20h x 4co per block of 160 threads.
// Thread: 4 c_out x 4 w pixels register-blocked.
// ============================================================
#define TW 32
#define TH 20
#define COB 4
#define SIN_ST 40

__global__ __launch_bounds__(160) void k_conv(float* __restrict__ out,
                                              const float* __restrict__ wgt,
                                              const float* __restrict__ bias) {
    __shared__ float s_in[26 * SIN_ST];
    __shared__ float s_w[COB * 49];
    int bx = blockIdx.x, by = blockIdx.y;
    int z = blockIdx.z;
    int b = z >> 4, cog = z & 15;
    int tid = threadIdx.x;
    int wg = tid & 7, py = tid >> 3;   // wg 0..7, py 0..19
    int wbase = wg * 4;
    int h0 = by * TH - 3, w0 = bx * TW - 3;
    float acc[16];
#pragma unroll
    for (int i = 0; i < 16; ++i) acc[i] = 0.0f;
    const float* inb = g_avg + (size_t)b * CC * HW;

    for (int ci = 0; ci < CC; ++ci) {
        __syncthreads();
        const float* src = inb + ci * HW;
        for (int i = tid; i < 26 * 38; i += 160) {
            int r = i / 38, c = i % 38;
            int gh = h0 + r, gw = w0 + c;
            float v = 0.0f;
            if (gh >= 0 && gh < HH && gw >= 0 && gw < WW) v = src[gh * WW + gw];
            s_in[r * SIN_ST + c] = v;
        }
        for (int i = tid; i < COB * 49; i += 160) {
            int co = i / 49, k = i % 49;
            s_w[i] = wgt[(size_t)((cog * COB + co) * CC + ci) * 49 + k];
        }
        __syncthreads();
#pragma unroll
        for (int ky = 0; ky < 7; ++ky) {
            float in[10];
            const float4* rp = reinterpret_cast<const float4*>(&s_in[(py + ky) * SIN_ST + wbase]);
            float4 a = rp[0];
            float4 bq = rp[1];
            float2 cq = *reinterpret_cast<const float2*>(&s_in[(py + ky) * SIN_ST + wbase + 8]);
            in[0] = a.x;  in[1] = a.y;  in[2] = a.z;  in[3] = a.w;
            in[4] = bq.x; in[5] = bq.y; in[6] = bq.z; in[7] = bq.w;
            in[8] = cq.x; in[9] = cq.y;
#pragma unroll
            for (int co = 0; co < COB; ++co) {
#pragma unroll
                for (int kx = 0; kx < 7; ++kx) {
                    float wv = s_w[co * 49 + ky * 7 + kx];
#pragma unroll
                    for (int wi = 0; wi < 4; ++wi)
                        acc[co * 4 + wi] = fmaf(in[kx + wi], wv, acc[co * 4 + wi]);
                }
            }
        }
    }

    int oh = by * TH + py;  // always < 100 (5 * 20 exact)
#pragma unroll
    for (int co = 0; co < COB; ++co) {
        int och = cog * COB + co;
        float bv = bias[och];
#pragma unroll
        for (int wi = 0; wi < 4; ++wi) {
            int ow = bx * TW + wbase + wi;  // always < 352 (11 * 32 exact)
            out[(size_t)((b * CC + och) * HH + oh) * WW + ow] = acc[co * 4 + wi] + bv;
        }
    }
}

// ============================================================
extern "C" void kernel_launch(void* const* d_in, const int* in_sizes, int n_in,
                              void* d_out, int out_size) {
    const float* x   = (const float*)d_in[0];  // (10,64,100,352)
    const float* psm = (const float*)d_in[1];  // (10,2,100,352)
    // d_in[2] record_len: unused
    const float* pt  = (const float*)d_in[3];  // (2,5,5,4,4)
    const float* fw  = (const float*)d_in[4];  // (64,64,7,7)
    const float* fb  = (const float*)d_in[5];  // (64,)
    float* out = (float*)d_out;                // (2,64,100,352)

    k_confwarp<<<dim3(HH, NIMG), WW>>>(psm, pt);
    k_select<<<NIMG, 256>>>();
    k_warpacc<<<dim3(HH, 4, BB), WW>>>(x, pt);
    k_conv<<<dim3(WW / TW, HH / TH, BB * 16), 160>>>(out, fw, fb);
}

// round 3
// speedup vs baseline: 1.1880x; 1.1880x over previous
#include <cuda_runtime.h>
#include <math.h>

#define NIMG 10
#define BB 2
#define LL 5
#define CC 64
#define HH 100
#define WW 352
#define HW 35200
#define KSEL 8800

// ---- scratch (static device globals; no allocation) ----
__device__ float g_confw[NIMG * HW];   // warped confidence (bit-exact vs XLA)
__device__ float g_thr[NIMG];          // per-sample K-th largest conf value
__device__ float g_avg[BB * CC * HW];  // (1/L) * sum_l sparse_l, per batch

// scale constants, computed in double then rounded to f32 (matches Python)
#define S01 ((float)(100.0 / 352.0))
#define S02 ((float)(2.0 / (2.0 * 0.4 * 352.0)))
#define S10 ((float)(352.0 / 100.0))
#define S12 ((float)(2.0 / (2.0 * 0.4 * 100.0)))
#define CXW ((float)(2.0 / 352.0))
#define CYH ((float)(2.0 / 100.0))

// packed fp32x2 ops (sm_100+): two IEEE fp32 FMAs per instruction
#define FMA_F32X2(d, a, b, c) \
    asm("fma.rn.f32x2 %0, %1, %2, %3;" : "=l"(d) : "l"(a), "l"(b), "l"(c))
#define PACK_F32X2(out, lo, hi) \
    asm("mov.b64 %0, {%1, %2};" : "=l"(out) : "r"(__float_as_uint(lo)), "r"(__float_as_uint(hi)))
#define UNPACK_F32X2(lo, hi, in) \
    { unsigned int _ulo, _uhi; \
      asm("mov.b64 {%0, %1}, %2;" : "=r"(_ulo), "=r"(_uhi) : "l"(in)); \
      lo = __uint_as_float(_ulo); hi = __uint_as_float(_uhi); }

// theta = pairwise_t_matrix[b, 0, l, :2, [0,1,3]] * scale  (fast path, non-strict)
__device__ __forceinline__ void get_theta(const float* __restrict__ pt, int b, int l, float th[6]) {
    const float* p = pt + b * (LL * LL * 16) + l * 16;  // i = 0
    th[0] = p[0];
    th[1] = p[1] * S01;
    th[2] = p[3] * S02;
    th[3] = p[4] * S10;
    th[4] = p[5];
    th[5] = p[7] * S12;
}

// ---- XLA f32 tanh (Eigen-style rational approx, uncontracted mul/add) ----
__device__ __forceinline__ float xla_tanh(float x) {
    float cx = fminf(fmaxf(x, -7.90531110763549805f), 7.90531110763549805f);
    float x2 = __fmul_rn(cx, cx);
    float p = -2.76076847742355e-16f;
    p = __fadd_rn(__fmul_rn(p, x2), 2.00018790482477e-13f);
    p = __fadd_rn(__fmul_rn(p, x2), -8.60467152213735e-11f);
    p = __fadd_rn(__fmul_rn(p, x2), 5.12229709037114e-08f);
    p = __fadd_rn(__fmul_rn(p, x2), 1.48572235717979e-05f);
    p = __fadd_rn(__fmul_rn(p, x2), 6.37261928875436e-04f);
    p = __fadd_rn(__fmul_rn(p, x2), 4.89352455891786e-03f);
    float num = __fmul_rn(cx, p);
    float q = 1.19825839466702e-06f;
    q = __fadd_rn(__fmul_rn(q, x2), 1.18534705686654e-04f);
    q = __fadd_rn(__fmul_rn(q, x2), 2.26843463243900e-03f);
    q = __fadd_rn(__fmul_rn(q, x2), 4.89352518554385e-03f);
    float r = __fdiv_rn(num, q);
    return (fabsf(x) < 0.0004f) ? x : r;
}

// XLA LogisticExpander: logistic(x) = 0.5 + 0.5 * tanh(0.5 * x) (0.5 mults exact)
__device__ __forceinline__ float xla_sigmoid(float x) {
    return __fadd_rn(0.5f, __fmul_rn(0.5f, xla_tanh(__fmul_rn(0.5f, x))));
}

// ============================================================
// Kernel 1: warp conf = sigmoid(max(psm over 2 ch)), bilinear.
// STRICT fp32 replication of the XLA op sequence (feeds the top-K mask).
// grid (H, N), block W
// ============================================================
__global__ __launch_bounds__(WW) void k_confwarp(const float* __restrict__ psm,
                                                 const float* __restrict__ pt) {
    int h = blockIdx.x, n = blockIdx.y, w = threadIdx.x;
    int b = n / LL, l = n % LL;
    const float* p = pt + b * (LL * LL * 16) + l * 16;
    float th0 = p[0];                    // * 1.0 exact
    float th1 = __fmul_rn(p[1], S01);
    float th2 = __fmul_rn(p[3], S02);
    float th3 = __fmul_rn(p[4], S10);
    float th4 = p[5];                    // * 1.0 exact
    float th5 = __fmul_rn(p[7], S12);

    float gx = __fsub_rn(__fmul_rn(__fadd_rn((float)w, 0.5f), CXW), 1.0f);
    float gy = __fsub_rn(__fmul_rn(__fadd_rn((float)h, 0.5f), CYH), 1.0f);
    float src_x = __fadd_rn(__fadd_rn(__fmul_rn(th0, gx), __fmul_rn(th1, gy)), th2);
    float src_y = __fadd_rn(__fadd_rn(__fmul_rn(th3, gx), __fmul_rn(th4, gy)), th5);
    float px = __fsub_rn(__fmul_rn(__fadd_rn(src_x, 1.0f), 176.0f), 0.5f);
    float py = __fsub_rn(__fmul_rn(__fadd_rn(src_y, 1.0f), 50.0f), 0.5f);
    float x0 = floorf(px), y0 = floorf(py);
    float wx1 = __fsub_rn(px, x0), wx0 = __fsub_rn(1.0f, wx1);
    float wy1 = __fsub_rn(py, y0), wy0 = __fsub_rn(1.0f, wy1);

    const float* base = psm + (size_t)n * 2 * HW;
    float acc = 0.0f;
#pragma unroll
    for (int dy = 0; dy < 2; ++dy) {
#pragma unroll
        for (int dx = 0; dx < 2; ++dx) {
            float yy = dy ? __fadd_rn(y0, 1.0f) : y0;   // exact
            float xx = dx ? __fadd_rn(x0, 1.0f) : x0;   // exact
            if (yy >= 0.0f && yy <= (float)(HH - 1) && xx >= 0.0f && xx <= (float)(WW - 1)) {
                int yi = (int)yy, xi = (int)xx;
                float m = fmaxf(base[yi * WW + xi], base[HW + yi * WW + xi]);
                float s = xla_sigmoid(m);
                float wgt = __fmul_rn(dy ? wy1 : wy0, dx ? wx1 : wx0);
                acc = __fadd_rn(acc, __fmul_rn(s, wgt));
            }
        }
    }
    g_confw[n * HW + h * WW + w] = acc;
}

// ============================================================
// Kernel 2: exact K-th largest of g_confw[n] via 4x8-bit MSB radix select.
// ============================================================
__global__ __launch_bounds__(256) void k_select() {
    int n = blockIdx.x;
    const float* v = g_confw + n * HW;
    __shared__ unsigned int hist[256];
    __shared__ unsigned int s_prefix, s_krem;
    if (threadIdx.x == 0) { s_prefix = 0u; s_krem = KSEL; }
    __syncthreads();
    for (int pass = 0; pass < 4; ++pass) {
        int shift = 24 - pass * 8;
        unsigned int pmask = (pass == 0) ? 0u : (0xFFFFFFFFu << (shift + 8));
        for (int i = threadIdx.x; i < 256; i += blockDim.x) hist[i] = 0u;
        __syncthreads();
        unsigned int prefix = s_prefix;
        for (int i = threadIdx.x; i < HW; i += blockDim.x) {
            unsigned int key = __float_as_uint(v[i]);
            if ((key & pmask) == prefix) atomicAdd(&hist[(key >> shift) & 255u], 1u);
        }
        __syncthreads();
        if (threadIdx.x == 0) {
            unsigned int krem = s_krem, c = 0u; int sel = 0;
            for (int bin = 255; bin >= 0; --bin) {
                c += hist[bin];
                if (c >= krem) { sel = bin; krem -= (c - hist[bin]); break; }
            }
            s_prefix = prefix | ((unsigned int)sel << shift);
            s_krem = krem;
        }
        __syncthreads();
    }
    if (threadIdx.x == 0) g_thr[n] = __uint_as_float(s_prefix);
}

// ============================================================
// Kernel 3: warp x + mask + (1/L)-accumulate over l. grid (H, 4, B), block W
// ============================================================
__global__ __launch_bounds__(WW) void k_warpacc(const float* __restrict__ x,
                                                const float* __restrict__ pt) {
    int h = blockIdx.x, cg = blockIdx.y, b = blockIdx.z, w = threadIdx.x;
    float acc[16];
#pragma unroll
    for (int i = 0; i < 16; ++i) acc[i] = 0.0f;
    float gx = (w + 0.5f) * (2.0f / WW) - 1.0f;
    float gy = (h + 0.5f) * (2.0f / HH) - 1.0f;
    for (int l = 0; l < LL; ++l) {
        int n = b * LL + l;
        if (l != 0 && g_confw[n * HW + h * WW + w] < g_thr[n]) continue;
        float th[6];
        get_theta(pt, b, l, th);
        float px = (th[0] * gx + th[1] * gy + th[2] + 1.0f) * (WW * 0.5f) - 0.5f;
        float py = (th[3] * gx + th[4] * gy + th[5] + 1.0f) * (HH * 0.5f) - 0.5f;
        float x0 = floorf(px), y0 = floorf(py);
        float wx1 = px - x0, wx0 = 1.0f - wx1;
        float wy1 = py - y0, wy0 = 1.0f - wy1;
        bool vx0 = (x0 >= 0.0f) && (x0 <= (float)(WW - 1));
        bool vx1 = (x0 + 1.0f >= 0.0f) && (x0 + 1.0f <= (float)(WW - 1));
        bool vy0 = (y0 >= 0.0f) && (y0 <= (float)(HH - 1));
        bool vy1 = (y0 + 1.0f >= 0.0f) && (y0 + 1.0f <= (float)(HH - 1));
        int x0i = (int)fminf(fmaxf(x0, 0.0f), (float)(WW - 1));
        int x1i = (int)fminf(fmaxf(x0 + 1.0f, 0.0f), (float)(WW - 1));
        int y0i = (int)fminf(fmaxf(y0, 0.0f), (float)(HH - 1));
        int y1i = (int)fminf(fmaxf(y0 + 1.0f, 0.0f), (float)(HH - 1));
        float m00 = (vy0 && vx0) ? wy0 * wx0 * 0.2f : 0.0f;
        float m01 = (vy0 && vx1) ? wy0 * wx1 * 0.2f : 0.0f;
        float m10 = (vy1 && vx0) ? wy1 * wx0 * 0.2f : 0.0f;
        float m11 = (vy1 && vx1) ? wy1 * wx1 * 0.2f : 0.0f;
        int i00 = y0i * WW + x0i, i01 = y0i * WW + x1i;
        int i10 = y1i * WW + x0i, i11 = y1i * WW + x1i;
        const float* xb = x + (size_t)(n * CC + cg * 16) * HW;
#pragma unroll
        for (int c = 0; c < 16; ++c) {
            const float* xc = xb + c * HW;
            acc[c] += xc[i00] * m00 + xc[i01] * m01 + xc[i10] * m10 + xc[i11] * m11;
        }
    }
    int outbase = ((b * CC + cg * 16) * HH + h) * WW + w;
#pragma unroll
    for (int c = 0; c < 16; ++c) g_avg[outbase + c * HW] = acc[c];
}

// ============================================================
// Kernel 4: 7x7 conv (pad 3) over g_avg[b], 64->64 ch, + bias.
// Tile: 32w x 20h x 4co per block of 160 threads.
// Thread: 4 c_out x 4 w, with FFMA2 (fma.rn.f32x2) pairing the two fp32
// lanes over adjacent c_out. Weights staged as [ky][kx][co] so a co-pair
// is one aligned LDS.64; inputs broadcast-packed once per ky.
// ============================================================
#define TW 32
#define TH 20
#define COB 4
#define SIN_ST 40

__global__ __launch_bounds__(160) void k_conv(float* __restrict__ out,
                                              const float* __restrict__ wgt,
                                              const float* __restrict__ bias) {
    __shared__ float s_in[26 * SIN_ST];
    __shared__ float s_w[49 * COB];   // layout [ky*7+kx][co]
    int bx = blockIdx.x, by = blockIdx.y;
    int z = blockIdx.z;
    int b = z >> 4, cog = z & 15;
    int tid = threadIdx.x;
    int wg = tid & 7, py = tid >> 3;   // wg 0..7, py 0..19
    int wbase = wg * 4;
    int h0 = by * TH - 3, w0 = bx * TW - 3;

    unsigned long long acc2[8];        // [co2*4 + wi]: lanes = (co=2*co2, co=2*co2+1)
#pragma unroll
    for (int i = 0; i < 8; ++i) PACK_F32X2(acc2[i], 0.0f, 0.0f);

    const float* inb = g_avg + (size_t)b * CC * HW;

    for (int ci = 0; ci < CC; ++ci) {
        __syncthreads();
        const float* src = inb + ci * HW;
        for (int i = tid; i < 26 * 38; i += 160) {
            int r = i / 38, c = i % 38;
            int gh = h0 + r, gw = w0 + c;
            float v = 0.0f;
            if (gh >= 0 && gh < HH && gw >= 0 && gw < WW) v = src[gh * WW + gw];
            s_in[r * SIN_ST + c] = v;
        }
        // weights transposed: s_w[k*4 + co] = wgt[co_global][ci][k]
        for (int i = tid; i < 49 * COB; i += 160) {
            int co = i & 3, k = i >> 2;
            s_w[i] = wgt[(size_t)((cog * COB + co) * CC + ci) * 49 + k];
        }
        __syncthreads();
#pragma unroll
        for (int ky = 0; ky < 7; ++ky) {
            float in[10];
            const float4* rp = reinterpret_cast<const float4*>(&s_in[(py + ky) * SIN_ST + wbase]);
            float4 a = rp[0];
            float4 bq = rp[1];
            float2 cq = *reinterpret_cast<const float2*>(&s_in[(py + ky) * SIN_ST + wbase + 8]);
            in[0] = a.x;  in[1] = a.y;  in[2] = a.z;  in[3] = a.w;
            in[4] = bq.x; in[5] = bq.y; in[6] = bq.z; in[7] = bq.w;
            in[8] = cq.x; in[9] = cq.y;
            unsigned long long pin[10];
#pragma unroll
            for (int j = 0; j < 10; ++j) PACK_F32X2(pin[j], in[j], in[j]);
#pragma unroll
            for (int kx = 0; kx < 7; ++kx) {
#pragma unroll
                for (int co2 = 0; co2 < 2; ++co2) {
                    unsigned long long w2 =
                        *reinterpret_cast<const unsigned long long*>(&s_w[(ky * 7 + kx) * 4 + co2 * 2]);
#pragma unroll
                    for (int wi = 0; wi < 4; ++wi)
                        FMA_F32X2(acc2[co2 * 4 + wi], pin[kx + wi], w2, acc2[co2 * 4 + wi]);
                }
            }
        }
    }

    int oh = by * TH + py;  // always < 100
#pragma unroll
    for (int co2 = 0; co2 < 2; ++co2) {
        int och0 = cog * COB + co2 * 2;
        float bv0 = bias[och0], bv1 = bias[och0 + 1];
#pragma unroll
        for (int wi = 0; wi < 4; ++wi) {
            float a0, a1;
            UNPACK_F32X2(a0, a1, acc2[co2 * 4 + wi]);
            int ow = bx * TW + wbase + wi;  // always < 352
            out[(size_t)((b * CC + och0) * HH + oh) * WW + ow] = a0 + bv0;
            out[(size_t)((b * CC + och0 + 1) * HH + oh) * WW + ow] = a1 + bv1;
        }
    }
}

// ============================================================
extern "C" void kernel_launch(void* const* d_in, const int* in_sizes, int n_in,
                              void* d_out, int out_size) {
    const float* x   = (const float*)d_in[0];  // (10,64,100,352)
    const float* psm = (const float*)d_in[1];  // (10,2,100,352)
    // d_in[2] record_len: unused
    const float* pt  = (const float*)d_in[3];  // (2,5,5,4,4)
    const float* fw  = (const float*)d_in[4];  // (64,64,7,7)
    const float* fb  = (const float*)d_in[5];  // (64,)
    float* out = (float*)d_out;                // (2,64,100,352)

    k_confwarp<<<dim3(HH, NIMG), WW>>>(psm, pt);
    k_select<<<NIMG, 256>>>();
    k_warpacc<<<dim3(HH, 4, BB), WW>>>(x, pt);
    k_conv<<<dim3(WW / TW, HH / TH, BB * 16), 160>>>(out, fw, fb);
}

// round 4
// speedup vs baseline: 1.3447x; 1.1319x over previous
#include <cuda_runtime.h>
#include <math.h>

#define NIMG 10
#define BB 2
#define LL 5
#define CC 64
#define HH 100
#define WW 352
#define HW 35200
#define KSEL 8800

// ---- scratch (static device globals; no allocation) ----
__device__ float g_confw[NIMG * HW];   // warped confidence (bit-exact vs XLA)
__device__ float g_thr[NIMG];          // per-sample K-th largest conf value
__device__ float g_avg[BB * CC * HW];  // (1/L) * sum_l sparse_l, per batch

// scale constants, computed in double then rounded to f32 (matches Python)
#define S01 ((float)(100.0 / 352.0))
#define S02 ((float)(2.0 / (2.0 * 0.4 * 352.0)))
#define S10 ((float)(352.0 / 100.0))
#define S12 ((float)(2.0 / (2.0 * 0.4 * 100.0)))
#define CXW ((float)(2.0 / 352.0))
#define CYH ((float)(2.0 / 100.0))

// packed fp32x2 ops (sm_100+): two IEEE fp32 FMAs per instruction
#define FMA_F32X2(d, a, b, c) \
    asm("fma.rn.f32x2 %0, %1, %2, %3;" : "=l"(d) : "l"(a), "l"(b), "l"(c))
#define PACK_F32X2(out, lo, hi) \
    asm("mov.b64 %0, {%1, %2};" : "=l"(out) : "r"(__float_as_uint(lo)), "r"(__float_as_uint(hi)))
#define UNPACK_F32X2(lo, hi, in) \
    { unsigned int _ulo, _uhi; \
      asm("mov.b64 {%0, %1}, %2;" : "=r"(_ulo), "=r"(_uhi) : "l"(in)); \
      lo = __uint_as_float(_ulo); hi = __uint_as_float(_uhi); }

// theta = pairwise_t_matrix[b, 0, l, :2, [0,1,3]] * scale  (fast path, non-strict)
__device__ __forceinline__ void get_theta(const float* __restrict__ pt, int b, int l, float th[6]) {
    const float* p = pt + b * (LL * LL * 16) + l * 16;  // i = 0
    th[0] = p[0];
    th[1] = p[1] * S01;
    th[2] = p[3] * S02;
    th[3] = p[4] * S10;
    th[4] = p[5];
    th[5] = p[7] * S12;
}

// ---- XLA f32 tanh (Eigen-style rational approx, uncontracted mul/add) ----
__device__ __forceinline__ float xla_tanh(float x) {
    float cx = fminf(fmaxf(x, -7.90531110763549805f), 7.90531110763549805f);
    float x2 = __fmul_rn(cx, cx);
    float p = -2.76076847742355e-16f;
    p = __fadd_rn(__fmul_rn(p, x2), 2.00018790482477e-13f);
    p = __fadd_rn(__fmul_rn(p, x2), -8.60467152213735e-11f);
    p = __fadd_rn(__fmul_rn(p, x2), 5.12229709037114e-08f);
    p = __fadd_rn(__fmul_rn(p, x2), 1.48572235717979e-05f);
    p = __fadd_rn(__fmul_rn(p, x2), 6.37261928875436e-04f);
    p = __fadd_rn(__fmul_rn(p, x2), 4.89352455891786e-03f);
    float num = __fmul_rn(cx, p);
    float q = 1.19825839466702e-06f;
    q = __fadd_rn(__fmul_rn(q, x2), 1.18534705686654e-04f);
    q = __fadd_rn(__fmul_rn(q, x2), 2.26843463243900e-03f);
    q = __fadd_rn(__fmul_rn(q, x2), 4.89352518554385e-03f);
    float r = __fdiv_rn(num, q);
    return (fabsf(x) < 0.0004f) ? x : r;
}

// XLA LogisticExpander: logistic(x) = 0.5 + 0.5 * tanh(0.5 * x) (0.5 mults exact)
__device__ __forceinline__ float xla_sigmoid(float x) {
    return __fadd_rn(0.5f, __fmul_rn(0.5f, xla_tanh(__fmul_rn(0.5f, x))));
}

// ============================================================
// Kernel 1: warp conf = sigmoid(max(psm over 2 ch)), bilinear.
// STRICT fp32 replication of the XLA op sequence (feeds the top-K mask).
// grid (H, N), block W
// ============================================================
__global__ __launch_bounds__(WW) void k_confwarp(const float* __restrict__ psm,
                                                 const float* __restrict__ pt) {
    int h = blockIdx.x, n = blockIdx.y, w = threadIdx.x;
    int b = n / LL, l = n % LL;
    const float* p = pt + b * (LL * LL * 16) + l * 16;
    float th0 = p[0];                    // * 1.0 exact
    float th1 = __fmul_rn(p[1], S01);
    float th2 = __fmul_rn(p[3], S02);
    float th3 = __fmul_rn(p[4], S10);
    float th4 = p[5];                    // * 1.0 exact
    float th5 = __fmul_rn(p[7], S12);

    float gx = __fsub_rn(__fmul_rn(__fadd_rn((float)w, 0.5f), CXW), 1.0f);
    float gy = __fsub_rn(__fmul_rn(__fadd_rn((float)h, 0.5f), CYH), 1.0f);
    float src_x = __fadd_rn(__fadd_rn(__fmul_rn(th0, gx), __fmul_rn(th1, gy)), th2);
    float src_y = __fadd_rn(__fadd_rn(__fmul_rn(th3, gx), __fmul_rn(th4, gy)), th5);
    float px = __fsub_rn(__fmul_rn(__fadd_rn(src_x, 1.0f), 176.0f), 0.5f);
    float py = __fsub_rn(__fmul_rn(__fadd_rn(src_y, 1.0f), 50.0f), 0.5f);
    float x0 = floorf(px), y0 = floorf(py);
    float wx1 = __fsub_rn(px, x0), wx0 = __fsub_rn(1.0f, wx1);
    float wy1 = __fsub_rn(py, y0), wy0 = __fsub_rn(1.0f, wy1);

    const float* base = psm + (size_t)n * 2 * HW;
    float acc = 0.0f;
#pragma unroll
    for (int dy = 0; dy < 2; ++dy) {
#pragma unroll
        for (int dx = 0; dx < 2; ++dx) {
            float yy = dy ? __fadd_rn(y0, 1.0f) : y0;   // exact
            float xx = dx ? __fadd_rn(x0, 1.0f) : x0;   // exact
            if (yy >= 0.0f && yy <= (float)(HH - 1) && xx >= 0.0f && xx <= (float)(WW - 1)) {
                int yi = (int)yy, xi = (int)xx;
                float m = fmaxf(base[yi * WW + xi], base[HW + yi * WW + xi]);
                float s = xla_sigmoid(m);
                float wgt = __fmul_rn(dy ? wy1 : wy0, dx ? wx1 : wx0);
                acc = __fadd_rn(acc, __fmul_rn(s, wgt));
            }
        }
    }
    g_confw[n * HW + h * WW + w] = acc;
}

// ============================================================
// Kernel 2: exact K-th largest of g_confw[n] via 4x8-bit MSB radix select.
// ============================================================
__global__ __launch_bounds__(256) void k_select() {
    int n = blockIdx.x;
    const float* v = g_confw + n * HW;
    __shared__ unsigned int hist[256];
    __shared__ unsigned int s_prefix, s_krem;
    if (threadIdx.x == 0) { s_prefix = 0u; s_krem = KSEL; }
    __syncthreads();
    for (int pass = 0; pass < 4; ++pass) {
        int shift = 24 - pass * 8;
        unsigned int pmask = (pass == 0) ? 0u : (0xFFFFFFFFu << (shift + 8));
        for (int i = threadIdx.x; i < 256; i += blockDim.x) hist[i] = 0u;
        __syncthreads();
        unsigned int prefix = s_prefix;
        for (int i = threadIdx.x; i < HW; i += blockDim.x) {
            unsigned int key = __float_as_uint(v[i]);
            if ((key & pmask) == prefix) atomicAdd(&hist[(key >> shift) & 255u], 1u);
        }
        __syncthreads();
        if (threadIdx.x == 0) {
            unsigned int krem = s_krem, c = 0u; int sel = 0;
            for (int bin = 255; bin >= 0; --bin) {
                c += hist[bin];
                if (c >= krem) { sel = bin; krem -= (c - hist[bin]); break; }
            }
            s_prefix = prefix | ((unsigned int)sel << shift);
            s_krem = krem;
        }
        __syncthreads();
    }
    if (threadIdx.x == 0) g_thr[n] = __uint_as_float(s_prefix);
}

// ============================================================
// Kernel 3: warp x + mask + (1/L)-accumulate over l. grid (H, 4, B), block W
// ============================================================
__global__ __launch_bounds__(WW) void k_warpacc(const float* __restrict__ x,
                                                const float* __restrict__ pt) {
    int h = blockIdx.x, cg = blockIdx.y, b = blockIdx.z, w = threadIdx.x;
    float acc[16];
#pragma unroll
    for (int i = 0; i < 16; ++i) acc[i] = 0.0f;
    float gx = (w + 0.5f) * (2.0f / WW) - 1.0f;
    float gy = (h + 0.5f) * (2.0f / HH) - 1.0f;
    for (int l = 0; l < LL; ++l) {
        int n = b * LL + l;
        if (l != 0 && g_confw[n * HW + h * WW + w] < g_thr[n]) continue;
        float th[6];
        get_theta(pt, b, l, th);
        float px = (th[0] * gx + th[1] * gy + th[2] + 1.0f) * (WW * 0.5f) - 0.5f;
        float py = (th[3] * gx + th[4] * gy + th[5] + 1.0f) * (HH * 0.5f) - 0.5f;
        float x0 = floorf(px), y0 = floorf(py);
        float wx1 = px - x0, wx0 = 1.0f - wx1;
        float wy1 = py - y0, wy0 = 1.0f - wy1;
        bool vx0 = (x0 >= 0.0f) && (x0 <= (float)(WW - 1));
        bool vx1 = (x0 + 1.0f >= 0.0f) && (x0 + 1.0f <= (float)(WW - 1));
        bool vy0 = (y0 >= 0.0f) && (y0 <= (float)(HH - 1));
        bool vy1 = (y0 + 1.0f >= 0.0f) && (y0 + 1.0f <= (float)(HH - 1));
        int x0i = (int)fminf(fmaxf(x0, 0.0f), (float)(WW - 1));
        int x1i = (int)fminf(fmaxf(x0 + 1.0f, 0.0f), (float)(WW - 1));
        int y0i = (int)fminf(fmaxf(y0, 0.0f), (float)(HH - 1));
        int y1i = (int)fminf(fmaxf(y0 + 1.0f, 0.0f), (float)(HH - 1));
        float m00 = (vy0 && vx0) ? wy0 * wx0 * 0.2f : 0.0f;
        float m01 = (vy0 && vx1) ? wy0 * wx1 * 0.2f : 0.0f;
        float m10 = (vy1 && vx0) ? wy1 * wx0 * 0.2f : 0.0f;
        float m11 = (vy1 && vx1) ? wy1 * wx1 * 0.2f : 0.0f;
        int i00 = y0i * WW + x0i, i01 = y0i * WW + x1i;
        int i10 = y1i * WW + x0i, i11 = y1i * WW + x1i;
        const float* xb = x + (size_t)(n * CC + cg * 16) * HW;
#pragma unroll
        for (int c = 0; c < 16; ++c) {
            const float* xc = xb + c * HW;
            acc[c] += xc[i00] * m00 + xc[i01] * m01 + xc[i10] * m10 + xc[i11] * m11;
        }
    }
    int outbase = ((b * CC + cg * 16) * HH + h) * WW + w;
#pragma unroll
    for (int c = 0; c < 16; ++c) g_avg[outbase + c * HW] = acc[c];
}

// ============================================================
// Kernel 4: 7x7 conv (pad 3) over g_avg[b], 64->64 ch, + bias.
// Block: 320 threads = two co-halves sharing one input tile.
// Tile: 32w x 20h x 8co. Per-thread: 4co x 4w via FFMA2 over co pairs.
// Software-pipelined: global loads for ci+1 issued into registers before
// the compute of ci; STS to alternate smem buffer; one barrier per ci.
// ============================================================
#define TW 32
#define TH 20
#define COB 8
#define SIN_ST 40
#define TILE_N (26 * 38)   // 988 valid elements (stored strided SIN_ST)
#define WN (49 * COB)      // 392 weights per ci

__global__ __launch_bounds__(320) void k_conv(float* __restrict__ out,
                                              const float* __restrict__ wgt,
                                              const float* __restrict__ bias) {
    __shared__ float s_in[2][26 * SIN_ST];
    __shared__ float s_w[2][WN];       // layout [k][co(0..7)]
    int bx = blockIdx.x, by = blockIdx.y;
    int z = blockIdx.z;
    int b = z >> 3, cog = z & 7;       // 8 co-groups of 8
    int tid = threadIdx.x;
    int half = tid >= 160 ? 1 : 0;
    int ht = tid - half * 160;
    int wg = ht & 7, py = ht >> 3;     // wg 0..7, py 0..19
    int wbase = wg * 4;
    int h0 = by * TH - 3, w0 = bx * TW - 3;

    unsigned long long acc2[8];        // [co2*4 + wi]
#pragma unroll
    for (int i = 0; i < 8; ++i) PACK_F32X2(acc2[i], 0.0f, 0.0f);

    const float* inb = g_avg + (size_t)b * CC * HW;
    const float* wb = wgt + (size_t)(cog * COB) * CC * 49;

    // per-thread static load slots (i = tid + s*320)
    int lrow[4], lcol[4];
    bool lval[4];
#pragma unroll
    for (int s = 0; s < 4; ++s) {
        int i = tid + s * 320;
        int r = i / 38, c = i % 38;
        lrow[s] = r; lcol[s] = c;
        int gh = h0 + r, gw = w0 + c;
        lval[s] = (i < TILE_N) && gh >= 0 && gh < HH && gw >= 0 && gw < WW;
        // store clamped gmem offset for safe predicated load
        lrow[s] = (gh < 0) ? 0 : (gh >= HH ? HH - 1 : gh);
        lcol[s] = (gw < 0) ? 0 : (gw >= WW ? WW - 1 : gw);
    }
    int srow[4], scol[4];
#pragma unroll
    for (int s = 0; s < 4; ++s) {
        int i = tid + s * 320;
        srow[s] = (i < TILE_N) ? (i / 38) : 0;
        scol[s] = (i < TILE_N) ? (i % 38) : 0;
    }
    // weight slots: i = tid + s*320, s=0..1
    int wk0 = tid;                 // < 392 always (tid<320)
    int wk1 = tid + 320;           // valid if < 392
    bool wv1 = (wk1 < WN);
    // wgt index for slot: k = i >> 3 (since layout s_w[k*8+co]), co = i & 7
    // gmem: wb[(co*CC + ci)*49 + k]

    // ---- prologue: load ci = 0 into buffer 0 ----
    {
        const float* src = inb;  // ci = 0
#pragma unroll
        for (int s = 0; s < 4; ++s) {
            int i = tid + s * 320;
            if (i < TILE_N) {
                float v = lval[s] ? src[lrow[s] * WW + lcol[s]] : 0.0f;
                s_in[0][srow[s] * SIN_ST + scol[s]] = v;
            }
        }
        {
            int k = wk0 >> 3, co = wk0 & 7;
            s_w[0][wk0] = wb[(size_t)(co * CC + 0) * 49 + k];
        }
        if (wv1) {
            int k = wk1 >> 3, co = wk1 & 7;
            s_w[0][wk1] = wb[(size_t)(co * CC + 0) * 49 + k];
        }
    }
    __syncthreads();

    for (int ci = 0; ci < CC; ++ci) {
        int cur = ci & 1;
        // ---- issue prefetch loads for ci+1 (registers; latency hidden) ----
        float pf[4], pw0 = 0.0f, pw1 = 0.0f;
        bool have_next = (ci + 1 < CC);
        if (have_next) {
            const float* src = inb + (ci + 1) * HW;
#pragma unroll
            for (int s = 0; s < 4; ++s) {
                int i = tid + s * 320;
                pf[s] = (i < TILE_N && lval[s]) ? src[lrow[s] * WW + lcol[s]] : 0.0f;
            }
            {
                int k = wk0 >> 3, co = wk0 & 7;
                pw0 = wb[(size_t)(co * CC + (ci + 1)) * 49 + k];
            }
            if (wv1) {
                int k = wk1 >> 3, co = wk1 & 7;
                pw1 = wb[(size_t)(co * CC + (ci + 1)) * 49 + k];
            }
        }

        // ---- compute from buffer cur ----
        const float* sw = &s_w[cur][half * 4];   // this half's 4 co (2 pairs)
#pragma unroll
        for (int ky = 0; ky < 7; ++ky) {
            float in[10];
            const float4* rp = reinterpret_cast<const float4*>(&s_in[cur][(py + ky) * SIN_ST + wbase]);
            float4 a = rp[0];
            float4 bq = rp[1];
            float2 cq = *reinterpret_cast<const float2*>(&s_in[cur][(py + ky) * SIN_ST + wbase + 8]);
            in[0] = a.x;  in[1] = a.y;  in[2] = a.z;  in[3] = a.w;
            in[4] = bq.x; in[5] = bq.y; in[6] = bq.z; in[7] = bq.w;
            in[8] = cq.x; in[9] = cq.y;
            unsigned long long pin[10];
#pragma unroll
            for (int j = 0; j < 10; ++j) PACK_F32X2(pin[j], in[j], in[j]);
#pragma unroll
            for (int kx = 0; kx < 7; ++kx) {
#pragma unroll
                for (int co2 = 0; co2 < 2; ++co2) {
                    unsigned long long w2 =
                        *reinterpret_cast<const unsigned long long*>(&sw[(ky * 7 + kx) * 8 + co2 * 2]);
#pragma unroll
                    for (int wi = 0; wi < 4; ++wi)
                        FMA_F32X2(acc2[co2 * 4 + wi], pin[kx + wi], w2, acc2[co2 * 4 + wi]);
                }
            }
        }

        // ---- drain prefetch into alternate buffer ----
        if (have_next) {
            int nxt = cur ^ 1;
#pragma unroll
            for (int s = 0; s < 4; ++s) {
                int i = tid + s * 320;
                if (i < TILE_N) s_in[nxt][srow[s] * SIN_ST + scol[s]] = pf[s];
            }
            s_w[nxt][wk0] = pw0;
            if (wv1) s_w[nxt][wk1] = pw1;
            __syncthreads();
        }
    }

    int oh = by * TH + py;  // always < 100
#pragma unroll
    for (int co2 = 0; co2 < 2; ++co2) {
        int och0 = cog * COB + half * 4 + co2 * 2;
        float bv0 = bias[och0], bv1 = bias[och0 + 1];
#pragma unroll
        for (int wi = 0; wi < 4; ++wi) {
            float a0, a1;
            UNPACK_F32X2(a0, a1, acc2[co2 * 4 + wi]);
            int ow = bx * TW + wbase + wi;  // always < 352
            out[(size_t)((b * CC + och0) * HH + oh) * WW + ow] = a0 + bv0;
            out[(size_t)((b * CC + och0 + 1) * HH + oh) * WW + ow] = a1 + bv1;
        }
    }
}

// ============================================================
extern "C" void kernel_launch(void* const* d_in, const int* in_sizes, int n_in,
                              void* d_out, int out_size) {
    const float* x   = (const float*)d_in[0];  // (10,64,100,352)
    const float* psm = (const float*)d_in[1];  // (10,2,100,352)
    // d_in[2] record_len: unused
    const float* pt  = (const float*)d_in[3];  // (2,5,5,4,4)
    const float* fw  = (const float*)d_in[4];  // (64,64,7,7)
    const float* fb  = (const float*)d_in[5];  // (64,)
    float* out = (float*)d_out;                // (2,64,100,352)

    k_confwarp<<<dim3(HH, NIMG), WW>>>(psm, pt);
    k_select<<<NIMG, 256>>>();
    k_warpacc<<<dim3(HH, 4, BB), WW>>>(x, pt);
    k_conv<<<dim3(WW / TW, HH / TH, BB * 8), 320>>>(out, fw, fb);
}

// round 6
// speedup vs baseline: 1.8312x; 1.3618x over previous
#include <cuda_runtime.h>
#include <math.h>
#include <stdint.h>

#define NIMG 10
#define BB 2
#define LL 5
#define CC 64
#define HH 100
#define WW 352
#define HW 35200
#define KSEL 8800

// ---- scratch (static device globals; no allocation) ----
__device__ float g_confw[NIMG * HW];   // warped confidence (bit-exact vs XLA)
__device__ float g_thr[NIMG];          // per-sample K-th largest conf value
__device__ float g_avg[BB * CC * HW];  // (1/L) * sum_l sparse_l, per batch
// pre-split conv weights: [ci][co][k64] bf16 hi / lo planes (k>=49 zeroed)
__device__ unsigned short g_wp_hi[CC * CC * 64];
__device__ unsigned short g_wp_lo[CC * CC * 64];

// scale constants, computed in double then rounded to f32 (matches Python)
#define S01 ((float)(100.0 / 352.0))
#define S02 ((float)(2.0 / (2.0 * 0.4 * 352.0)))
#define S10 ((float)(352.0 / 100.0))
#define S12 ((float)(2.0 / (2.0 * 0.4 * 100.0)))
#define CXW ((float)(2.0 / 352.0))
#define CYH ((float)(2.0 / 100.0))

// ============================================================
// mma.sync / ldmatrix helpers (baseline PTX, sm_80+; OK on sm_103 plain)
// ============================================================
static __device__ __forceinline__ uint32_t smem_u32(const void* p) {
    uint32_t a;
    asm("{ .reg .u64 t; cvta.to.shared.u64 t, %1; cvt.u32.u64 %0, t; }" : "=r"(a) : "l"(p));
    return a;
}

#define LDMATRIX_X4(r, addr) \
    asm volatile("ldmatrix.sync.aligned.m8n8.x4.shared.b16 {%0,%1,%2,%3}, [%4];" \
        : "=r"((r)[0]), "=r"((r)[1]), "=r"((r)[2]), "=r"((r)[3]) : "r"(addr))

#define LDMATRIX_X2(r, addr) \
    asm volatile("ldmatrix.sync.aligned.m8n8.x2.shared.b16 {%0,%1}, [%2];" \
        : "=r"((r)[0]), "=r"((r)[1]) : "r"(addr))

#define MMA_B16(d, a, bfr) \
    asm volatile("mma.sync.aligned.m16n8k16.row.col.f32.bf16.bf16.f32 " \
        "{%0,%1,%2,%3}, {%4,%5,%6,%7}, {%8,%9}, {%0,%1,%2,%3};" \
        : "+f"((d)[0]), "+f"((d)[1]), "+f"((d)[2]), "+f"((d)[3]) \
        : "r"((a)[0]), "r"((a)[1]), "r"((a)[2]), "r"((a)[3]), "r"((bfr)[0]), "r"((bfr)[1]))

// ---- XLA f32 tanh (Eigen-style rational approx, uncontracted mul/add) ----
__device__ __forceinline__ float xla_tanh(float x) {
    float cx = fminf(fmaxf(x, -7.90531110763549805f), 7.90531110763549805f);
    float x2 = __fmul_rn(cx, cx);
    float p = -2.76076847742355e-16f;
    p = __fadd_rn(__fmul_rn(p, x2), 2.00018790482477e-13f);
    p = __fadd_rn(__fmul_rn(p, x2), -8.60467152213735e-11f);
    p = __fadd_rn(__fmul_rn(p, x2), 5.12229709037114e-08f);
    p = __fadd_rn(__fmul_rn(p, x2), 1.48572235717979e-05f);
    p = __fadd_rn(__fmul_rn(p, x2), 6.37261928875436e-04f);
    p = __fadd_rn(__fmul_rn(p, x2), 4.89352455891786e-03f);
    float num = __fmul_rn(cx, p);
    float q = 1.19825839466702e-06f;
    q = __fadd_rn(__fmul_rn(q, x2), 1.18534705686654e-04f);
    q = __fadd_rn(__fmul_rn(q, x2), 2.26843463243900e-03f);
    q = __fadd_rn(__fmul_rn(q, x2), 4.89352518554385e-03f);
    float r = __fdiv_rn(num, q);
    return (fabsf(x) < 0.0004f) ? x : r;
}
__device__ __forceinline__ float xla_sigmoid(float x) {
    return __fadd_rn(0.5f, __fmul_rn(0.5f, xla_tanh(__fmul_rn(0.5f, x))));
}

__device__ __forceinline__ void get_theta(const float* __restrict__ pt, int b, int l, float th[6]) {
    const float* p = pt + b * (LL * LL * 16) + l * 16;
    th[0] = p[0];
    th[1] = p[1] * S01;
    th[2] = p[3] * S02;
    th[3] = p[4] * S10;
    th[4] = p[5];
    th[5] = p[7] * S12;
}

// ============================================================
// Kernel 1: warp conf (strict XLA fp32 replication; feeds top-K mask)
// ============================================================
__global__ __launch_bounds__(WW) void k_confwarp(const float* __restrict__ psm,
                                                 const float* __restrict__ pt) {
    int h = blockIdx.x, n = blockIdx.y, w = threadIdx.x;
    int b = n / LL, l = n % LL;
    const float* p = pt + b * (LL * LL * 16) + l * 16;
    float th0 = p[0];
    float th1 = __fmul_rn(p[1], S01);
    float th2 = __fmul_rn(p[3], S02);
    float th3 = __fmul_rn(p[4], S10);
    float th4 = p[5];
    float th5 = __fmul_rn(p[7], S12);

    float gx = __fsub_rn(__fmul_rn(__fadd_rn((float)w, 0.5f), CXW), 1.0f);
    float gy = __fsub_rn(__fmul_rn(__fadd_rn((float)h, 0.5f), CYH), 1.0f);
    float src_x = __fadd_rn(__fadd_rn(__fmul_rn(th0, gx), __fmul_rn(th1, gy)), th2);
    float src_y = __fadd_rn(__fadd_rn(__fmul_rn(th3, gx), __fmul_rn(th4, gy)), th5);
    float px = __fsub_rn(__fmul_rn(__fadd_rn(src_x, 1.0f), 176.0f), 0.5f);
    float py = __fsub_rn(__fmul_rn(__fadd_rn(src_y, 1.0f), 50.0f), 0.5f);
    float x0 = floorf(px), y0 = floorf(py);
    float wx1 = __fsub_rn(px, x0), wx0 = __fsub_rn(1.0f, wx1);
    float wy1 = __fsub_rn(py, y0), wy0 = __fsub_rn(1.0f, wy1);

    const float* base = psm + (size_t)n * 2 * HW;
    float acc = 0.0f;
#pragma unroll
    for (int dy = 0; dy < 2; ++dy) {
#pragma unroll
        for (int dx = 0; dx < 2; ++dx) {
            float yy = dy ? __fadd_rn(y0, 1.0f) : y0;
            float xx = dx ? __fadd_rn(x0, 1.0f) : x0;
            if (yy >= 0.0f && yy <= (float)(HH - 1) && xx >= 0.0f && xx <= (float)(WW - 1)) {
                int yi = (int)yy, xi = (int)xx;
                float m = fmaxf(base[yi * WW + xi], base[HW + yi * WW + xi]);
                float s = xla_sigmoid(m);
                float wgt = __fmul_rn(dy ? wy1 : wy0, dx ? wx1 : wx0);
                acc = __fadd_rn(acc, __fmul_rn(s, wgt));
            }
        }
    }
    g_confw[n * HW + h * WW + w] = acc;
}

// ============================================================
// Kernel 2: exact K-th largest via 4x8-bit MSB radix select.
// ============================================================
__global__ __launch_bounds__(256) void k_select() {
    int n = blockIdx.x;
    const float* v = g_confw + n * HW;
    __shared__ unsigned int hist[256];
    __shared__ unsigned int s_prefix, s_krem;
    if (threadIdx.x == 0) { s_prefix = 0u; s_krem = KSEL; }
    __syncthreads();
    for (int pass = 0; pass < 4; ++pass) {
        int shift = 24 - pass * 8;
        unsigned int pmask = (pass == 0) ? 0u : (0xFFFFFFFFu << (shift + 8));
        for (int i = threadIdx.x; i < 256; i += blockDim.x) hist[i] = 0u;
        __syncthreads();
        unsigned int prefix = s_prefix;
        for (int i = threadIdx.x; i < HW; i += blockDim.x) {
            unsigned int key = __float_as_uint(v[i]);
            if ((key & pmask) == prefix) atomicAdd(&hist[(key >> shift) & 255u], 1u);
        }
        __syncthreads();
        if (threadIdx.x == 0) {
            unsigned int krem = s_krem, c = 0u; int sel = 0;
            for (int bin = 255; bin >= 0; --bin) {
                c += hist[bin];
                if (c >= krem) { sel = bin; krem -= (c - hist[bin]); break; }
            }
            s_prefix = prefix | ((unsigned int)sel << shift);
            s_krem = krem;
        }
        __syncthreads();
    }
    if (threadIdx.x == 0) g_thr[n] = __uint_as_float(s_prefix);
}

// ============================================================
// Kernel 3: warp x + mask + (1/L)-accumulate over l. grid (H, 4, B), block W
// ============================================================
__global__ __launch_bounds__(WW) void k_warpacc(const float* __restrict__ x,
                                                const float* __restrict__ pt) {
    int h = blockIdx.x, cg = blockIdx.y, b = blockIdx.z, w = threadIdx.x;
    float acc[16];
#pragma unroll
    for (int i = 0; i < 16; ++i) acc[i] = 0.0f;
    float gx = (w + 0.5f) * (2.0f / WW) - 1.0f;
    float gy = (h + 0.5f) * (2.0f / HH) - 1.0f;
    for (int l = 0; l < LL; ++l) {
        int n = b * LL + l;
        if (l != 0 && g_confw[n * HW + h * WW + w] < g_thr[n]) continue;
        float th[6];
        get_theta(pt, b, l, th);
        float px = (th[0] * gx + th[1] * gy + th[2] + 1.0f) * (WW * 0.5f) - 0.5f;
        float py = (th[3] * gx + th[4] * gy + th[5] + 1.0f) * (HH * 0.5f) - 0.5f;
        float x0 = floorf(px), y0 = floorf(py);
        float wx1 = px - x0, wx0 = 1.0f - wx1;
        float wy1 = py - y0, wy0 = 1.0f - wy1;
        bool vx0 = (x0 >= 0.0f) && (x0 <= (float)(WW - 1));
        bool vx1 = (x0 + 1.0f >= 0.0f) && (x0 + 1.0f <= (float)(WW - 1));
        bool vy0 = (y0 >= 0.0f) && (y0 <= (float)(HH - 1));
        bool vy1 = (y0 + 1.0f >= 0.0f) && (y0 + 1.0f <= (float)(HH - 1));
        int x0i = (int)fminf(fmaxf(x0, 0.0f), (float)(WW - 1));
        int x1i = (int)fminf(fmaxf(x0 + 1.0f, 0.0f), (float)(WW - 1));
        int y0i = (int)fminf(fmaxf(y0, 0.0f), (float)(HH - 1));
        int y1i = (int)fminf(fmaxf(y0 + 1.0f, 0.0f), (float)(HH - 1));
        float m00 = (vy0 && vx0) ? wy0 * wx0 * 0.2f : 0.0f;
        float m01 = (vy0 && vx1) ? wy0 * wx1 * 0.2f : 0.0f;
        float m10 = (vy1 && vx0) ? wy1 * wx0 * 0.2f : 0.0f;
        float m11 = (vy1 && vx1) ? wy1 * wx1 * 0.2f : 0.0f;
        int i00 = y0i * WW + x0i, i01 = y0i * WW + x1i;
        int i10 = y1i * WW + x0i, i11 = y1i * WW + x1i;
        const float* xb = x + (size_t)(n * CC + cg * 16) * HW;
#pragma unroll
        for (int c = 0; c < 16; ++c) {
            const float* xc = xb + c * HW;
            acc[c] += xc[i00] * m00 + xc[i01] * m01 + xc[i10] * m10 + xc[i11] * m11;
        }
    }
    int outbase = ((b * CC + cg * 16) * HH + h) * WW + w;
#pragma unroll
    for (int c = 0; c < 16; ++c) g_avg[outbase + c * HW] = acc[c];
}

// ============================================================
// Kernel 3b: pre-split conv weights into bf16 hi/lo planes, K padded 49->64.
// g_wp_*[ci][co][k]. grid 64 (ci), 256 threads.
// ============================================================
__global__ __launch_bounds__(256) void k_prepw(const float* __restrict__ fw) {
    int ci = blockIdx.x;
    for (int e = threadIdx.x; e < CC * 64; e += 256) {
        int co = e >> 6, k = e & 63;
        float v = (k < 49) ? fw[(size_t)(co * CC + ci) * 49 + k] : 0.0f;
        uint32_t u = __float_as_uint(v);
        float xl = v - __uint_as_float(u & 0xFFFF0000u);
        g_wp_hi[(size_t)ci * (CC * 64) + e] = (unsigned short)(u >> 16);
        g_wp_lo[(size_t)ci * (CC * 64) + e] = (unsigned short)(__float_as_uint(xl) >> 16);
    }
}

// ============================================================
// Kernel 4: 7x7 conv via mma.sync implicit GEMM (bf16 hi/lo 3-pass).
// Block tile: D[128 px (4h x 32w), 64 co]; K-loop over 64 ci (k=49 pad 64).
// 8 warps as 4(m) x 2(n): warp = 32px x 32co. 96 MMA / warp / ci.
// ============================================================
#define ASTRIDE 144                      // bytes per A row (72 bf16; conflict-free)
#define AS_HI 0
#define AS_LO 18432
#define BS_OFF(buf, plane) (36864 + (buf) * 18432 + (plane) * 9216)
#define PATCH_OFF(buf) (73728 + (buf) * 1536)
#define SMEM_TC 76800

__device__ __forceinline__ void buildA(unsigned char* smem, const float* patch, int tid) {
    int px = tid >> 1, half = tid & 1;
    const float* pb = patch + (px >> 5) * 38 + (px & 31);
    unsigned char* ahp = smem + AS_HI + px * ASTRIDE;
    unsigned char* alp = smem + AS_LO + px * ASTRIDE;
#pragma unroll
    for (int jj = 0; jj < 13; ++jj) {
        if (half == 0 && jj >= 12) break;
        int k0 = half ? (24 + 2 * jj) : (2 * jj);
        float f0 = pb[(k0 / 7) * 38 + (k0 % 7)];
        int k1 = k0 + 1;
        float f1 = (k1 < 49) ? pb[(k1 / 7) * 38 + (k1 % 7)] : 0.0f;
        uint32_t u0 = __float_as_uint(f0), u1 = __float_as_uint(f1);
        uint32_t hi = __byte_perm(u0, u1, 0x7632);
        float l0 = f0 - __uint_as_float(u0 & 0xFFFF0000u);
        float l1 = f1 - __uint_as_float(u1 & 0xFFFF0000u);
        uint32_t lo = __byte_perm(__float_as_uint(l0), __float_as_uint(l1), 0x7632);
        *(uint32_t*)(ahp + k0 * 2) = hi;
        *(uint32_t*)(alp + k0 * 2) = lo;
    }
}

__global__ void __launch_bounds__(256, 2) k_conv_mma(float* __restrict__ out,
                                                     const float* __restrict__ bias) {
    extern __shared__ unsigned char smem[];
    uint32_t sb = smem_u32(smem);
    int tid = threadIdx.x;
    int lane = tid & 31, wrp = tid >> 5;
    int mw = wrp & 3, nw = wrp >> 2;
    int b = blockIdx.z;
    int h0 = blockIdx.y * 4, w0 = blockIdx.x * 32;

    // zero A planes once (covers K pad cols 50..63 permanently)
    for (int i = tid; i < (2 * 18432) / 4; i += 256) ((uint32_t*)smem)[i] = 0u;

    float acc[2][4][4];
#pragma unroll
    for (int mt = 0; mt < 2; ++mt)
#pragma unroll
        for (int nt = 0; nt < 4; ++nt)
#pragma unroll
            for (int r = 0; r < 4; ++r) acc[mt][nt][r] = 0.0f;

    // ldmatrix lane-offsets
    int tl = lane >> 3;
    int a_roff = (lane & 7) + (tl & 1) * 8;      // A: row within 16-row tile
    int a_coff = (tl >> 1) * 8;                  // A: k offset 0/8
    int b_roff = lane & 7;                       // B: co row within 8 (lanes mod 16)
    int b_coff = ((lane >> 3) & 1) * 8;          // B: k offset 0/8

    // patch load slot
    int p_i0 = tid, p_i1 = tid + 256;
    int p_r0 = p_i0 / 38, p_c0 = p_i0 % 38;
    int p_r1 = p_i1 / 38, p_c1 = p_i1 % 38;
    bool p_v1 = p_i1 < 380;
    int gh0 = h0 - 3 + p_r0, gw0 = w0 - 3 + p_c0;
    int gh1 = h0 - 3 + p_r1, gw1 = w0 - 3 + p_c1;
    bool p_in0 = gh0 >= 0 && gh0 < HH && gw0 >= 0 && gw0 < WW;
    bool p_in1 = p_v1 && gh1 >= 0 && gh1 < HH && gw1 >= 0 && gw1 < WW;

    // B copy slots: u16 index s = (tid + c*256)*8 -> co = s>>6, k = s&63
    int b_co0 = tid >> 3, b_k0 = (tid & 7) * 8;
    int b_co1 = 32 + (tid >> 3);

    const float* inb = g_avg + (size_t)b * CC * HW;

    // ---- prologue: stage patch(0), B(0) into buffer 0 ----
    {
        float* pdst = (float*)(smem + PATCH_OFF(0));
        pdst[p_i0] = p_in0 ? inb[gh0 * WW + gw0] : 0.0f;
        if (p_v1) pdst[p_i1] = p_in1 ? inb[gh1 * WW + gw1] : 0.0f;
        const float4* sh = (const float4*)(g_wp_hi);
        const float4* sl = (const float4*)(g_wp_lo);
        float4* dh = (float4*)(smem + BS_OFF(0, 0));
        float4* dl = (float4*)(smem + BS_OFF(0, 1));
        // float4 = 8 u16; row stride 144B = 9 float4
        dh[b_co0 * 9 + (b_k0 >> 3)] = sh[tid];
        dh[b_co1 * 9 + (b_k0 >> 3)] = sh[tid + 256];
        dl[b_co0 * 9 + (b_k0 >> 3)] = sl[tid];
        dl[b_co1 * 9 + (b_k0 >> 3)] = sl[tid + 256];
    }
    __syncthreads();
    buildA(smem, (const float*)(smem + PATCH_OFF(0)), tid);

    for (int ci = 0; ci < CC; ++ci) {
        int buf = ci & 1;
        __syncthreads();   // A(ci), B(ci) visible; stale buffers free

        // ---- issue prefetch LDGs for ci+1 ----
        float pf0 = 0.0f, pf1 = 0.0f;
        float4 vh0, vh1, vl0, vl1;
        bool have_next = (ci + 1 < CC);
        if (have_next) {
            const float* src = inb + (ci + 1) * HW;
            pf0 = p_in0 ? src[gh0 * WW + gw0] : 0.0f;
            pf1 = p_in1 ? src[gh1 * WW + gw1] : 0.0f;
            const float4* sh = (const float4*)(g_wp_hi + (size_t)(ci + 1) * (CC * 64));
            const float4* sl = (const float4*)(g_wp_lo + (size_t)(ci + 1) * (CC * 64));
            vh0 = sh[tid]; vh1 = sh[tid + 256];
            vl0 = sl[tid]; vl1 = sl[tid + 256];
        }

        // ---- compute: 96 MMAs ----
        uint32_t bhi = sb + BS_OFF(buf, 0);
        uint32_t blo = sb + BS_OFF(buf, 1);
#pragma unroll
        for (int j = 0; j < 4; ++j) {
            uint32_t Ah[2][4], Al[2][4];
#pragma unroll
            for (int mt = 0; mt < 2; ++mt) {
                uint32_t arow = (uint32_t)(mw * 32 + mt * 16 + a_roff);
                uint32_t acol = (uint32_t)(j * 16 + a_coff);
                LDMATRIX_X4(Ah[mt], sb + AS_HI + arow * ASTRIDE + acol * 2);
                LDMATRIX_X4(Al[mt], sb + AS_LO + arow * ASTRIDE + acol * 2);
            }
#pragma unroll
            for (int nt = 0; nt < 4; ++nt) {
                uint32_t brow = (uint32_t)(nw * 32 + nt * 8 + b_roff);
                uint32_t bcol = (uint32_t)(j * 16 + b_coff);
                uint32_t Bh[2], Bl[2];
                LDMATRIX_X2(Bh, bhi + brow * ASTRIDE + bcol * 2);
                LDMATRIX_X2(Bl, blo + brow * ASTRIDE + bcol * 2);
#pragma unroll
                for (int mt = 0; mt < 2; ++mt) {
                    MMA_B16(acc[mt][nt], Ah[mt], Bh);
                    MMA_B16(acc[mt][nt], Ah[mt], Bl);
                    MMA_B16(acc[mt][nt], Al[mt], Bh);
                }
            }
        }

        // ---- drain prefetch into alternate buffers, rebuild A ----
        if (have_next) {
            int nb = buf ^ 1;
            float* pdst = (float*)(smem + PATCH_OFF(nb));
            pdst[p_i0] = pf0;
            if (p_v1) pdst[p_i1] = pf1;
            float4* dh = (float4*)(smem + BS_OFF(nb, 0));
            float4* dl = (float4*)(smem + BS_OFF(nb, 1));
            dh[b_co0 * 9 + (b_k0 >> 3)] = vh0;
            dh[b_co1 * 9 + (b_k0 >> 3)] = vh1;
            dl[b_co0 * 9 + (b_k0 >> 3)] = vl0;
            dl[b_co1 * 9 + (b_k0 >> 3)] = vl1;
            __syncthreads();
            buildA(smem, (const float*)(smem + PATCH_OFF(nb)), tid);
        }
    }

    // ---- epilogue ----
    int g = lane >> 2, tig = lane & 3;
    float* o = out + (size_t)b * CC * HW;
#pragma unroll
    for (int mt = 0; mt < 2; ++mt) {
        int r0 = mw * 32 + mt * 16 + g;
        int oh0 = h0 + (r0 >> 5), ow0 = w0 + (r0 & 31);
        int r1 = r0 + 8;
        int oh1 = h0 + (r1 >> 5), ow1 = w0 + (r1 & 31);
#pragma unroll
        for (int nt = 0; nt < 4; ++nt) {
            int co = nw * 32 + nt * 8 + tig * 2;
            float bv0 = __ldg(&bias[co]), bv1 = __ldg(&bias[co + 1]);
            o[(size_t)co * HW + oh0 * WW + ow0] = acc[mt][nt][0] + bv0;
            o[(size_t)(co + 1) * HW + oh0 * WW + ow0] = acc[mt][nt][1] + bv1;
            o[(size_t)co * HW + oh1 * WW + ow1] = acc[mt][nt][2] + bv0;
            o[(size_t)(co + 1) * HW + oh1 * WW + ow1] = acc[mt][nt][3] + bv1;
        }
    }
}

// ============================================================
extern "C" void kernel_launch(void* const* d_in, const int* in_sizes, int n_in,
                              void* d_out, int out_size) {
    const float* x   = (const float*)d_in[0];  // (10,64,100,352)
    const float* psm = (const float*)d_in[1];  // (10,2,100,352)
    // d_in[2] record_len: unused
    const float* pt  = (const float*)d_in[3];  // (2,5,5,4,4)
    const float* fw  = (const float*)d_in[4];  // (64,64,7,7)
    const float* fb  = (const float*)d_in[5];  // (64,)
    float* out = (float*)d_out;                // (2,64,100,352)

    static int smem_set = 0;
    if (!smem_set) {
        cudaFuncSetAttribute(k_conv_mma, cudaFuncAttributeMaxDynamicSharedMemorySize, SMEM_TC);
        smem_set = 1;
    }

    k_prepw<<<CC, 256>>>(fw);
    k_confwarp<<<dim3(HH, NIMG), WW>>>(psm, pt);
    k_select<<<NIMG, 256>>>();
    k_warpacc<<<dim3(HH, 4, BB), WW>>>(x, pt);
    k_conv_mma<<<dim3(WW / 32, HH / 4, BB), 256, SMEM_TC>>>(out, fb);
}

// round 7
// speedup vs baseline: 2.1336x; 1.1651x over previous
#include <cuda_runtime.h>
#include <math.h>
#include <stdint.h>

#define NIMG 10
#define BB 2
#define LL 5
#define CC 64
#define HH 100
#define WW 352
#define HW 35200
#define KSEL 8800

// ---- scratch (static device globals; no allocation) ----
__device__ float g_confw[NIMG * HW];   // warped confidence (bit-exact vs XLA)
__device__ float g_thr[NIMG];          // per-sample K-th largest conf value
__device__ float g_avg[BB * CC * HW];  // (1/L) * sum_l sparse_l, per batch
// pre-split conv weights per tap: [t][co][ci] bf16 hi / lo planes
__device__ unsigned short g_wt_hi[49 * CC * CC];
__device__ unsigned short g_wt_lo[49 * CC * CC];

// scale constants, computed in double then rounded to f32 (matches Python)
#define S01 ((float)(100.0 / 352.0))
#define S02 ((float)(2.0 / (2.0 * 0.4 * 352.0)))
#define S10 ((float)(352.0 / 100.0))
#define S12 ((float)(2.0 / (2.0 * 0.4 * 100.0)))
#define CXW ((float)(2.0 / 352.0))
#define CYH ((float)(2.0 / 100.0))

// ============================================================
// mma.sync / ldmatrix helpers (baseline PTX, sm_80+; OK on sm_103 plain)
// ============================================================
static __device__ __forceinline__ uint32_t smem_u32(const void* p) {
    uint32_t a;
    asm("{ .reg .u64 t; cvta.to.shared.u64 t, %1; cvt.u32.u64 %0, t; }" : "=r"(a) : "l"(p));
    return a;
}

#define LDMATRIX_X4(r, addr) \
    asm volatile("ldmatrix.sync.aligned.m8n8.x4.shared.b16 {%0,%1,%2,%3}, [%4];" \
        : "=r"((r)[0]), "=r"((r)[1]), "=r"((r)[2]), "=r"((r)[3]) : "r"(addr))

#define LDMATRIX_X2(r, addr) \
    asm volatile("ldmatrix.sync.aligned.m8n8.x2.shared.b16 {%0,%1}, [%2];" \
        : "=r"((r)[0]), "=r"((r)[1]) : "r"(addr))

#define MMA_B16(d, a, bfr) \
    asm volatile("mma.sync.aligned.m16n8k16.row.col.f32.bf16.bf16.f32 " \
        "{%0,%1,%2,%3}, {%4,%5,%6,%7}, {%8,%9}, {%0,%1,%2,%3};" \
        : "+f"((d)[0]), "+f"((d)[1]), "+f"((d)[2]), "+f"((d)[3]) \
        : "r"((a)[0]), "r"((a)[1]), "r"((a)[2]), "r"((a)[3]), "r"((bfr)[0]), "r"((bfr)[1]))

// ---- XLA f32 tanh (Eigen-style rational approx, uncontracted mul/add) ----
__device__ __forceinline__ float xla_tanh(float x) {
    float cx = fminf(fmaxf(x, -7.90531110763549805f), 7.90531110763549805f);
    float x2 = __fmul_rn(cx, cx);
    float p = -2.76076847742355e-16f;
    p = __fadd_rn(__fmul_rn(p, x2), 2.00018790482477e-13f);
    p = __fadd_rn(__fmul_rn(p, x2), -8.60467152213735e-11f);
    p = __fadd_rn(__fmul_rn(p, x2), 5.12229709037114e-08f);
    p = __fadd_rn(__fmul_rn(p, x2), 1.48572235717979e-05f);
    p = __fadd_rn(__fmul_rn(p, x2), 6.37261928875436e-04f);
    p = __fadd_rn(__fmul_rn(p, x2), 4.89352455891786e-03f);
    float num = __fmul_rn(cx, p);
    float q = 1.19825839466702e-06f;
    q = __fadd_rn(__fmul_rn(q, x2), 1.18534705686654e-04f);
    q = __fadd_rn(__fmul_rn(q, x2), 2.26843463243900e-03f);
    q = __fadd_rn(__fmul_rn(q, x2), 4.89352518554385e-03f);
    float r = __fdiv_rn(num, q);
    return (fabsf(x) < 0.0004f) ? x : r;
}
__device__ __forceinline__ float xla_sigmoid(float x) {
    return __fadd_rn(0.5f, __fmul_rn(0.5f, xla_tanh(__fmul_rn(0.5f, x))));
}

__device__ __forceinline__ void get_theta(const float* __restrict__ pt, int b, int l, float th[6]) {
    const float* p = pt + b * (LL * LL * 16) + l * 16;
    th[0] = p[0];
    th[1] = p[1] * S01;
    th[2] = p[3] * S02;
    th[3] = p[4] * S10;
    th[4] = p[5];
    th[5] = p[7] * S12;
}

// ============================================================
// Kernel 1: warp conf (strict XLA fp32 replication; feeds top-K mask)
// ============================================================
__global__ __launch_bounds__(WW) void k_confwarp(const float* __restrict__ psm,
                                                 const float* __restrict__ pt) {
    int h = blockIdx.x, n = blockIdx.y, w = threadIdx.x;
    int b = n / LL, l = n % LL;
    const float* p = pt + b * (LL * LL * 16) + l * 16;
    float th0 = p[0];
    float th1 = __fmul_rn(p[1], S01);
    float th2 = __fmul_rn(p[3], S02);
    float th3 = __fmul_rn(p[4], S10);
    float th4 = p[5];
    float th5 = __fmul_rn(p[7], S12);

    float gx = __fsub_rn(__fmul_rn(__fadd_rn((float)w, 0.5f), CXW), 1.0f);
    float gy = __fsub_rn(__fmul_rn(__fadd_rn((float)h, 0.5f), CYH), 1.0f);
    float src_x = __fadd_rn(__fadd_rn(__fmul_rn(th0, gx), __fmul_rn(th1, gy)), th2);
    float src_y = __fadd_rn(__fadd_rn(__fmul_rn(th3, gx), __fmul_rn(th4, gy)), th5);
    float px = __fsub_rn(__fmul_rn(__fadd_rn(src_x, 1.0f), 176.0f), 0.5f);
    float py = __fsub_rn(__fmul_rn(__fadd_rn(src_y, 1.0f), 50.0f), 0.5f);
    float x0 = floorf(px), y0 = floorf(py);
    float wx1 = __fsub_rn(px, x0), wx0 = __fsub_rn(1.0f, wx1);
    float wy1 = __fsub_rn(py, y0), wy0 = __fsub_rn(1.0f, wy1);

    const float* base = psm + (size_t)n * 2 * HW;
    float acc = 0.0f;
#pragma unroll
    for (int dy = 0; dy < 2; ++dy) {
#pragma unroll
        for (int dx = 0; dx < 2; ++dx) {
            float yy = dy ? __fadd_rn(y0, 1.0f) : y0;
            float xx = dx ? __fadd_rn(x0, 1.0f) : x0;
            if (yy >= 0.0f && yy <= (float)(HH - 1) && xx >= 0.0f && xx <= (float)(WW - 1)) {
                int yi = (int)yy, xi = (int)xx;
                float m = fmaxf(base[yi * WW + xi], base[HW + yi * WW + xi]);
                float s = xla_sigmoid(m);
                float wgt = __fmul_rn(dy ? wy1 : wy0, dx ? wx1 : wx0);
                acc = __fadd_rn(acc, __fmul_rn(s, wgt));
            }
        }
    }
    g_confw[n * HW + h * WW + w] = acc;
}

// ============================================================
// Kernel 2: exact K-th largest via 4x8-bit MSB radix select.
// ============================================================
__global__ __launch_bounds__(256) void k_select() {
    int n = blockIdx.x;
    const float* v = g_confw + n * HW;
    __shared__ unsigned int hist[256];
    __shared__ unsigned int s_prefix, s_krem;
    if (threadIdx.x == 0) { s_prefix = 0u; s_krem = KSEL; }
    __syncthreads();
    for (int pass = 0; pass < 4; ++pass) {
        int shift = 24 - pass * 8;
        unsigned int pmask = (pass == 0) ? 0u : (0xFFFFFFFFu << (shift + 8));
        for (int i = threadIdx.x; i < 256; i += blockDim.x) hist[i] = 0u;
        __syncthreads();
        unsigned int prefix = s_prefix;
        for (int i = threadIdx.x; i < HW; i += blockDim.x) {
            unsigned int key = __float_as_uint(v[i]);
            if ((key & pmask) == prefix) atomicAdd(&hist[(key >> shift) & 255u], 1u);
        }
        __syncthreads();
        if (threadIdx.x == 0) {
            unsigned int krem = s_krem, c = 0u; int sel = 0;
            for (int bin = 255; bin >= 0; --bin) {
                c += hist[bin];
                if (c >= krem) { sel = bin; krem -= (c - hist[bin]); break; }
            }
            s_prefix = prefix | ((unsigned int)sel << shift);
            s_krem = krem;
        }
        __syncthreads();
    }
    if (threadIdx.x == 0) g_thr[n] = __uint_as_float(s_prefix);
}

// ============================================================
// Kernel 3: warp x + mask + (1/L)-accumulate over l. grid (H, 4, B), block W
// ============================================================
__global__ __launch_bounds__(WW) void k_warpacc(const float* __restrict__ x,
                                                const float* __restrict__ pt) {
    int h = blockIdx.x, cg = blockIdx.y, b = blockIdx.z, w = threadIdx.x;
    float acc[16];
#pragma unroll
    for (int i = 0; i < 16; ++i) acc[i] = 0.0f;
    float gx = (w + 0.5f) * (2.0f / WW) - 1.0f;
    float gy = (h + 0.5f) * (2.0f / HH) - 1.0f;
    for (int l = 0; l < LL; ++l) {
        int n = b * LL + l;
        if (l != 0 && g_confw[n * HW + h * WW + w] < g_thr[n]) continue;
        float th[6];
        get_theta(pt, b, l, th);
        float px = (th[0] * gx + th[1] * gy + th[2] + 1.0f) * (WW * 0.5f) - 0.5f;
        float py = (th[3] * gx + th[4] * gy + th[5] + 1.0f) * (HH * 0.5f) - 0.5f;
        float x0 = floorf(px), y0 = floorf(py);
        float wx1 = px - x0, wx0 = 1.0f - wx1;
        float wy1 = py - y0, wy0 = 1.0f - wy1;
        bool vx0 = (x0 >= 0.0f) && (x0 <= (float)(WW - 1));
        bool vx1 = (x0 + 1.0f >= 0.0f) && (x0 + 1.0f <= (float)(WW - 1));
        bool vy0 = (y0 >= 0.0f) && (y0 <= (float)(HH - 1));
        bool vy1 = (y0 + 1.0f >= 0.0f) && (y0 + 1.0f <= (float)(HH - 1));
        int x0i = (int)fminf(fmaxf(x0, 0.0f), (float)(WW - 1));
        int x1i = (int)fminf(fmaxf(x0 + 1.0f, 0.0f), (float)(WW - 1));
        int y0i = (int)fminf(fmaxf(y0, 0.0f), (float)(HH - 1));
        int y1i = (int)fminf(fmaxf(y0 + 1.0f, 0.0f), (float)(HH - 1));
        float m00 = (vy0 && vx0) ? wy0 * wx0 * 0.2f : 0.0f;
        float m01 = (vy0 && vx1) ? wy0 * wx1 * 0.2f : 0.0f;
        float m10 = (vy1 && vx0) ? wy1 * wx0 * 0.2f : 0.0f;
        float m11 = (vy1 && vx1) ? wy1 * wx1 * 0.2f : 0.0f;
        int i00 = y0i * WW + x0i, i01 = y0i * WW + x1i;
        int i10 = y1i * WW + x0i, i11 = y1i * WW + x1i;
        const float* xb = x + (size_t)(n * CC + cg * 16) * HW;
#pragma unroll
        for (int c = 0; c < 16; ++c) {
            const float* xc = xb + c * HW;
            acc[c] += xc[i00] * m00 + xc[i01] * m01 + xc[i10] * m10 + xc[i11] * m11;
        }
    }
    int outbase = ((b * CC + cg * 16) * HH + h) * WW + w;
#pragma unroll
    for (int c = 0; c < 16; ++c) g_avg[outbase + c * HW] = acc[c];
}

// ============================================================
// Kernel 3b: pre-split conv weights per tap: g_wt_*[t][co][ci], bf16 hi/lo.
// grid 49 (t), 256 threads.
// ============================================================
__global__ __launch_bounds__(256) void k_prepw(const float* __restrict__ fw) {
    int t = blockIdx.x;
    for (int e = threadIdx.x; e < CC * CC; e += 256) {
        int co = e >> 6, ci = e & 63;
        float v = fw[(size_t)(co * CC + ci) * 49 + t];
        uint32_t u = __float_as_uint(v);
        float xl = v - __uint_as_float(u & 0xFFFF0000u);
        g_wt_hi[(size_t)t * (CC * CC) + e] = (unsigned short)(u >> 16);
        g_wt_lo[(size_t)t * (CC * CC) + e] = (unsigned short)(__float_as_uint(xl) >> 16);
    }
}

// ============================================================
// Kernel 4: 7x7 conv via mma.sync implicit GEMM, taps-outer / K=ci.
// Block tile: D[128 px (4h x 32w), 64 co]. A_ext (380 ext px x 64 ci,
// bf16 hi/lo) built ONCE; 49 taps read shifted rows via ldmatrix.
// B (per tap, [co][ci]) double-buffered, prefetched during MMAs.
// 8 warps as 4(m) x 2(n); 96 MMA / warp / tap; 1 barrier / tap.
// ============================================================
#define ASTRIDE 144
#define AS_HI 0
#define AS_LO 54720                       // 380 * 144
#define BS_OFF(buf, plane) (109440 + (buf) * 18432 + (plane) * 9216)
#define SMEM_TC 146304

__global__ void __launch_bounds__(256, 1) k_conv_mma(float* __restrict__ out,
                                                     const float* __restrict__ bias) {
    extern __shared__ unsigned char smem[];
    uint32_t sb = smem_u32(smem);
    int tid = threadIdx.x;
    int lane = tid & 31, wrp = tid >> 5;
    int mw = wrp & 3, nw = wrp >> 2;
    int b = blockIdx.z;
    int h0 = blockIdx.y * 4, w0 = blockIdx.x * 32;

    float acc[2][4][4];
#pragma unroll
    for (int mt = 0; mt < 2; ++mt)
#pragma unroll
        for (int nt = 0; nt < 4; ++nt)
#pragma unroll
            for (int r = 0; r < 4; ++r) acc[mt][nt][r] = 0.0f;

    // ldmatrix lane-offsets (same fragment conventions as the validated R5 kernel)
    int tl = lane >> 3;
    int a_roff = (lane & 7) + (tl & 1) * 8;
    int a_coff = (tl >> 1) * 8;
    int b_roff = lane & 7;
    int b_coff = ((lane >> 3) & 1) * 8;

    // per-lane A base addresses (ext-pixel row of this lane's fragment row)
    uint32_t aBase[2];
#pragma unroll
    for (int mt = 0; mt < 2; ++mt) {
        int px = mw * 32 + mt * 16 + a_roff;       // 0..127 block-pixel
        int pr = px >> 5, pc = px & 31;
        aBase[mt] = sb + AS_HI + (uint32_t)(pr * 38 + pc) * ASTRIDE + (uint32_t)a_coff * 2;
    }
    uint32_t bBase = (uint32_t)(nw * 32 + b_roff) * ASTRIDE + (uint32_t)b_coff * 2;

    // B copy slots: float4 s = tid (co = tid>>3, ci4 = tid&7), and co+32 at tid+256
    int b_co0 = tid >> 3, b_f4 = tid & 7;

    const float* inb = g_avg + (size_t)b * CC * HW;

    // ---- build A_ext once: 380 ext px x 64 ci, bf16 hi/lo ----
#pragma unroll 4
    for (int it = 0; it < 96; ++it) {
        int idx = tid + it * 256;                 // 0..24575 = 64 ci * 384 slots
        int ci = idx / 384, p = idx - ci * 384;
        if (p < 380) {
            int er = p / 38, ec = p - er * 38;
            int gh = h0 - 3 + er, gw = w0 - 3 + ec;
            float v = 0.0f;
            if (gh >= 0 && gh < HH && gw >= 0 && gw < WW) v = inb[(size_t)ci * HW + gh * WW + gw];
            uint32_t u = __float_as_uint(v);
            float xl = v - __uint_as_float(u & 0xFFFF0000u);
            *(unsigned short*)(smem + AS_HI + p * ASTRIDE + ci * 2) = (unsigned short)(u >> 16);
            *(unsigned short*)(smem + AS_LO + p * ASTRIDE + ci * 2) =
                (unsigned short)(__float_as_uint(xl) >> 16);
        }
    }
    // ---- stage B(tap 0) into buffer 0 ----
    {
        const float4* sh = (const float4*)(g_wt_hi);
        const float4* sl = (const float4*)(g_wt_lo);
        float4* dh = (float4*)(smem + BS_OFF(0, 0));
        float4* dl = (float4*)(smem + BS_OFF(0, 1));
        dh[b_co0 * 9 + b_f4] = sh[tid];
        dh[(b_co0 + 32) * 9 + b_f4] = sh[tid + 256];
        dl[b_co0 * 9 + b_f4] = sl[tid];
        dl[(b_co0 + 32) * 9 + b_f4] = sl[tid + 256];
    }
    __syncthreads();

    int tapoff = 0;   // (ky*38 + kx) * ASTRIDE
    int kx = 0;
    for (int t = 0; t < 49; ++t) {
        int buf = t & 1;
        bool have_next = (t + 1 < 49);
        float4 vh0, vh1, vl0, vl1;
        if (have_next) {
            const float4* sh = (const float4*)(g_wt_hi + (size_t)(t + 1) * (CC * CC));
            const float4* sl = (const float4*)(g_wt_lo + (size_t)(t + 1) * (CC * CC));
            vh0 = sh[tid]; vh1 = sh[tid + 256];
            vl0 = sl[tid]; vl1 = sl[tid + 256];
        }

        uint32_t bhi = sb + BS_OFF(buf, 0) + bBase;
        uint32_t blo = sb + BS_OFF(buf, 1) + bBase;
#pragma unroll
        for (int j = 0; j < 4; ++j) {
            uint32_t Ah[2][4], Al[2][4];
#pragma unroll
            for (int mt = 0; mt < 2; ++mt) {
                uint32_t aa = aBase[mt] + (uint32_t)tapoff + (uint32_t)j * 32;
                LDMATRIX_X4(Ah[mt], aa);
                LDMATRIX_X4(Al[mt], aa + (AS_LO - AS_HI));
            }
#pragma unroll
            for (int nt = 0; nt < 4; ++nt) {
                uint32_t bo = (uint32_t)(nt * 8) * ASTRIDE + (uint32_t)j * 32;
                uint32_t Bh[2], Bl[2];
                LDMATRIX_X2(Bh, bhi + bo);
                LDMATRIX_X2(Bl, blo + bo);
#pragma unroll
                for (int mt = 0; mt < 2; ++mt) {
                    MMA_B16(acc[mt][nt], Ah[mt], Bh);
                    MMA_B16(acc[mt][nt], Ah[mt], Bl);
                    MMA_B16(acc[mt][nt], Al[mt], Bh);
                }
            }
        }

        if (have_next) {
            int nb = buf ^ 1;
            float4* dh = (float4*)(smem + BS_OFF(nb, 0));
            float4* dl = (float4*)(smem + BS_OFF(nb, 1));
            dh[b_co0 * 9 + b_f4] = vh0;
            dh[(b_co0 + 32) * 9 + b_f4] = vh1;
            dl[b_co0 * 9 + b_f4] = vl0;
            dl[(b_co0 + 32) * 9 + b_f4] = vl1;
        }
        __syncthreads();

        // advance tap
        ++kx;
        if (kx == 7) { kx = 0; tapoff += 32 * ASTRIDE; }  // next ky: +(38-6)
        else tapoff += ASTRIDE;
    }

    // ---- epilogue ----
    int g = lane >> 2, tig = lane & 3;
    float* o = out + (size_t)b * CC * HW;
#pragma unroll
    for (int mt = 0; mt < 2; ++mt) {
        int r0 = mw * 32 + mt * 16 + g;
        int oh0 = h0 + (r0 >> 5), ow0 = w0 + (r0 & 31);
        int r1 = r0 + 8;
        int oh1 = h0 + (r1 >> 5), ow1 = w0 + (r1 & 31);
#pragma unroll
        for (int nt = 0; nt < 4; ++nt) {
            int co = nw * 32 + nt * 8 + tig * 2;
            float bv0 = __ldg(&bias[co]), bv1 = __ldg(&bias[co + 1]);
            o[(size_t)co * HW + oh0 * WW + ow0] = acc[mt][nt][0] + bv0;
            o[(size_t)(co + 1) * HW + oh0 * WW + ow0] = acc[mt][nt][1] + bv1;
            o[(size_t)co * HW + oh1 * WW + ow1] = acc[mt][nt][2] + bv0;
            o[(size_t)(co + 1) * HW + oh1 * WW + ow1] = acc[mt][nt][3] + bv1;
        }
    }
}

// ============================================================
extern "C" void kernel_launch(void* const* d_in, const int* in_sizes, int n_in,
                              void* d_out, int out_size) {
    const float* x   = (const float*)d_in[0];  // (10,64,100,352)
    const float* psm = (const float*)d_in[1];  // (10,2,100,352)
    // d_in[2] record_len: unused
    const float* pt  = (const float*)d_in[3];  // (2,5,5,4,4)
    const float* fw  = (const float*)d_in[4];  // (64,64,7,7)
    const float* fb  = (const float*)d_in[5];  // (64,)
    float* out = (float*)d_out;                // (2,64,100,352)

    cudaFuncSetAttribute(k_conv_mma, cudaFuncAttributeMaxDynamicSharedMemorySize, SMEM_TC);

    k_prepw<<<49, 256>>>(fw);
    k_confwarp<<<dim3(HH, NIMG), WW>>>(psm, pt);
    k_select<<<NIMG, 256>>>();
    k_warpacc<<<dim3(HH, 4, BB), WW>>>(x, pt);
    k_conv_mma<<<dim3(WW / 32, HH / 4, BB), 256, SMEM_TC>>>(out, fb);
}

// round 8
// speedup vs baseline: 2.5062x; 1.1747x over previous
#include <cuda_runtime.h>
#include <cuda_fp16.h>
#include <math.h>
#include <stdint.h>

#define NIMG 10
#define BB 2
#define LL 5
#define CC 64
#define HH 100
#define WW 352
#define HW 35200
#define KSEL 8800

// ---- scratch (static device globals; no allocation) ----
__device__ float g_confw[NIMG * HW];   // warped confidence (bit-exact vs XLA)
__device__ float g_thr[NIMG];          // per-sample K-th largest conf value
__device__ float g_avg[BB * CC * HW];  // (1/L) * sum_l sparse_l, per batch
// conv weights per tap, fp16: [t][co][ci]
__device__ unsigned short g_wt[49 * CC * CC];

// scale constants, computed in double then rounded to f32 (matches Python)
#define S01 ((float)(100.0 / 352.0))
#define S02 ((float)(2.0 / (2.0 * 0.4 * 352.0)))
#define S10 ((float)(352.0 / 100.0))
#define S12 ((float)(2.0 / (2.0 * 0.4 * 100.0)))
#define CXW ((float)(2.0 / 352.0))
#define CYH ((float)(2.0 / 100.0))

// ============================================================
// mma.sync / ldmatrix helpers (baseline PTX, sm_80+; OK on sm_103 plain)
// ============================================================
static __device__ __forceinline__ uint32_t smem_u32(const void* p) {
    uint32_t a;
    asm("{ .reg .u64 t; cvta.to.shared.u64 t, %1; cvt.u32.u64 %0, t; }" : "=r"(a) : "l"(p));
    return a;
}

#define LDMATRIX_X4(r, addr) \
    asm volatile("ldmatrix.sync.aligned.m8n8.x4.shared.b16 {%0,%1,%2,%3}, [%4];" \
        : "=r"((r)[0]), "=r"((r)[1]), "=r"((r)[2]), "=r"((r)[3]) : "r"(addr))

#define LDMATRIX_X2(r, addr) \
    asm volatile("ldmatrix.sync.aligned.m8n8.x2.shared.b16 {%0,%1}, [%2];" \
        : "=r"((r)[0]), "=r"((r)[1]) : "r"(addr))

#define MMA_F16(d, a, bfr) \
    asm volatile("mma.sync.aligned.m16n8k16.row.col.f32.f16.f16.f32 " \
        "{%0,%1,%2,%3}, {%4,%5,%6,%7}, {%8,%9}, {%0,%1,%2,%3};" \
        : "+f"((d)[0]), "+f"((d)[1]), "+f"((d)[2]), "+f"((d)[3]) \
        : "r"((a)[0]), "r"((a)[1]), "r"((a)[2]), "r"((a)[3]), "r"((bfr)[0]), "r"((bfr)[1]))

// ---- XLA f32 tanh (Eigen-style rational approx, uncontracted mul/add) ----
__device__ __forceinline__ float xla_tanh(float x) {
    float cx = fminf(fmaxf(x, -7.90531110763549805f), 7.90531110763549805f);
    float x2 = __fmul_rn(cx, cx);
    float p = -2.76076847742355e-16f;
    p = __fadd_rn(__fmul_rn(p, x2), 2.00018790482477e-13f);
    p = __fadd_rn(__fmul_rn(p, x2), -8.60467152213735e-11f);
    p = __fadd_rn(__fmul_rn(p, x2), 5.12229709037114e-08f);
    p = __fadd_rn(__fmul_rn(p, x2), 1.48572235717979e-05f);
    p = __fadd_rn(__fmul_rn(p, x2), 6.37261928875436e-04f);
    p = __fadd_rn(__fmul_rn(p, x2), 4.89352455891786e-03f);
    float num = __fmul_rn(cx, p);
    float q = 1.19825839466702e-06f;
    q = __fadd_rn(__fmul_rn(q, x2), 1.18534705686654e-04f);
    q = __fadd_rn(__fmul_rn(q, x2), 2.26843463243900e-03f);
    q = __fadd_rn(__fmul_rn(q, x2), 4.89352518554385e-03f);
    float r = __fdiv_rn(num, q);
    return (fabsf(x) < 0.0004f) ? x : r;
}
__device__ __forceinline__ float xla_sigmoid(float x) {
    return __fadd_rn(0.5f, __fmul_rn(0.5f, xla_tanh(__fmul_rn(0.5f, x))));
}

__device__ __forceinline__ void get_theta(const float* __restrict__ pt, int b, int l, float th[6]) {
    const float* p = pt + b * (LL * LL * 16) + l * 16;
    th[0] = p[0];
    th[1] = p[1] * S01;
    th[2] = p[3] * S02;
    th[3] = p[4] * S10;
    th[4] = p[5];
    th[5] = p[7] * S12;
}

// ============================================================
// Kernel 1: warp conf (strict XLA fp32 replication; feeds top-K mask)
// ============================================================
__global__ __launch_bounds__(WW) void k_confwarp(const float* __restrict__ psm,
                                                 const float* __restrict__ pt) {
    int h = blockIdx.x, n = blockIdx.y, w = threadIdx.x;
    int b = n / LL, l = n % LL;
    const float* p = pt + b * (LL * LL * 16) + l * 16;
    float th0 = p[0];
    float th1 = __fmul_rn(p[1], S01);
    float th2 = __fmul_rn(p[3], S02);
    float th3 = __fmul_rn(p[4], S10);
    float th4 = p[5];
    float th5 = __fmul_rn(p[7], S12);

    float gx = __fsub_rn(__fmul_rn(__fadd_rn((float)w, 0.5f), CXW), 1.0f);
    float gy = __fsub_rn(__fmul_rn(__fadd_rn((float)h, 0.5f), CYH), 1.0f);
    float src_x = __fadd_rn(__fadd_rn(__fmul_rn(th0, gx), __fmul_rn(th1, gy)), th2);
    float src_y = __fadd_rn(__fadd_rn(__fmul_rn(th3, gx), __fmul_rn(th4, gy)), th5);
    float px = __fsub_rn(__fmul_rn(__fadd_rn(src_x, 1.0f), 176.0f), 0.5f);
    float py = __fsub_rn(__fmul_rn(__fadd_rn(src_y, 1.0f), 50.0f), 0.5f);
    float x0 = floorf(px), y0 = floorf(py);
    float wx1 = __fsub_rn(px, x0), wx0 = __fsub_rn(1.0f, wx1);
    float wy1 = __fsub_rn(py, y0), wy0 = __fsub_rn(1.0f, wy1);

    const float* base = psm + (size_t)n * 2 * HW;
    float acc = 0.0f;
#pragma unroll
    for (int dy = 0; dy < 2; ++dy) {
#pragma unroll
        for (int dx = 0; dx < 2; ++dx) {
            float yy = dy ? __fadd_rn(y0, 1.0f) : y0;
            float xx = dx ? __fadd_rn(x0, 1.0f) : x0;
            if (yy >= 0.0f && yy <= (float)(HH - 1) && xx >= 0.0f && xx <= (float)(WW - 1)) {
                int yi = (int)yy, xi = (int)xx;
                float m = fmaxf(base[yi * WW + xi], base[HW + yi * WW + xi]);
                float s = xla_sigmoid(m);
                float wgt = __fmul_rn(dy ? wy1 : wy0, dx ? wx1 : wx0);
                acc = __fadd_rn(acc, __fmul_rn(s, wgt));
            }
        }
    }
    g_confw[n * HW + h * WW + w] = acc;
}

// ============================================================
// Kernel 2: exact K-th largest via 4x8-bit MSB radix select.
// ============================================================
__global__ __launch_bounds__(256) void k_select() {
    int n = blockIdx.x;
    const float* v = g_confw + n * HW;
    __shared__ unsigned int hist[256];
    __shared__ unsigned int s_prefix, s_krem;
    if (threadIdx.x == 0) { s_prefix = 0u; s_krem = KSEL; }
    __syncthreads();
    for (int pass = 0; pass < 4; ++pass) {
        int shift = 24 - pass * 8;
        unsigned int pmask = (pass == 0) ? 0u : (0xFFFFFFFFu << (shift + 8));
        for (int i = threadIdx.x; i < 256; i += blockDim.x) hist[i] = 0u;
        __syncthreads();
        unsigned int prefix = s_prefix;
        for (int i = threadIdx.x; i < HW; i += blockDim.x) {
            unsigned int key = __float_as_uint(v[i]);
            if ((key & pmask) == prefix) atomicAdd(&hist[(key >> shift) & 255u], 1u);
        }
        __syncthreads();
        if (threadIdx.x == 0) {
            unsigned int krem = s_krem, c = 0u; int sel = 0;
            for (int bin = 255; bin >= 0; --bin) {
                c += hist[bin];
                if (c >= krem) { sel = bin; krem -= (c - hist[bin]); break; }
            }
            s_prefix = prefix | ((unsigned int)sel << shift);
            s_krem = krem;
        }
        __syncthreads();
    }
    if (threadIdx.x == 0) g_thr[n] = __uint_as_float(s_prefix);
}

// ============================================================
// Kernel 3: warp x + mask + (1/L)-accumulate over l. grid (H, 4, B), block W
// ============================================================
__global__ __launch_bounds__(WW) void k_warpacc(const float* __restrict__ x,
                                                const float* __restrict__ pt) {
    int h = blockIdx.x, cg = blockIdx.y, b = blockIdx.z, w = threadIdx.x;
    float acc[16];
#pragma unroll
    for (int i = 0; i < 16; ++i) acc[i] = 0.0f;
    float gx = (w + 0.5f) * (2.0f / WW) - 1.0f;
    float gy = (h + 0.5f) * (2.0f / HH) - 1.0f;
    for (int l = 0; l < LL; ++l) {
        int n = b * LL + l;
        if (l != 0 && g_confw[n * HW + h * WW + w] < g_thr[n]) continue;
        float th[6];
        get_theta(pt, b, l, th);
        float px = (th[0] * gx + th[1] * gy + th[2] + 1.0f) * (WW * 0.5f) - 0.5f;
        float py = (th[3] * gx + th[4] * gy + th[5] + 1.0f) * (HH * 0.5f) - 0.5f;
        float x0 = floorf(px), y0 = floorf(py);
        float wx1 = px - x0, wx0 = 1.0f - wx1;
        float wy1 = py - y0, wy0 = 1.0f - wy1;
        bool vx0 = (x0 >= 0.0f) && (x0 <= (float)(WW - 1));
        bool vx1 = (x0 + 1.0f >= 0.0f) && (x0 + 1.0f <= (float)(WW - 1));
        bool vy0 = (y0 >= 0.0f) && (y0 <= (float)(HH - 1));
        bool vy1 = (y0 + 1.0f >= 0.0f) && (y0 + 1.0f <= (float)(HH - 1));
        int x0i = (int)fminf(fmaxf(x0, 0.0f), (float)(WW - 1));
        int x1i = (int)fminf(fmaxf(x0 + 1.0f, 0.0f), (float)(WW - 1));
        int y0i = (int)fminf(fmaxf(y0, 0.0f), (float)(HH - 1));
        int y1i = (int)fminf(fmaxf(y0 + 1.0f, 0.0f), (float)(HH - 1));
        float m00 = (vy0 && vx0) ? wy0 * wx0 * 0.2f : 0.0f;
        float m01 = (vy0 && vx1) ? wy0 * wx1 * 0.2f : 0.0f;
        float m10 = (vy1 && vx0) ? wy1 * wx0 * 0.2f : 0.0f;
        float m11 = (vy1 && vx1) ? wy1 * wx1 * 0.2f : 0.0f;
        int i00 = y0i * WW + x0i, i01 = y0i * WW + x1i;
        int i10 = y1i * WW + x0i, i11 = y1i * WW + x1i;
        const float* xb = x + (size_t)(n * CC + cg * 16) * HW;
#pragma unroll
        for (int c = 0; c < 16; ++c) {
            const float* xc = xb + c * HW;
            acc[c] += xc[i00] * m00 + xc[i01] * m01 + xc[i10] * m10 + xc[i11] * m11;
        }
    }
    int outbase = ((b * CC + cg * 16) * HH + h) * WW + w;
#pragma unroll
    for (int c = 0; c < 16; ++c) g_avg[outbase + c * HW] = acc[c];
}

// ============================================================
// Kernel 3b: weights -> fp16 per tap: g_wt[t][co][ci]. grid 49, 256 thr.
// ============================================================
__global__ __launch_bounds__(256) void k_prepw(const float* __restrict__ fw) {
    int t = blockIdx.x;
    for (int e = threadIdx.x; e < CC * CC; e += 256) {
        int co = e >> 6, ci = e & 63;
        float v = fw[(size_t)(co * CC + ci) * 49 + t];
        g_wt[(size_t)t * (CC * CC) + e] = __half_as_ushort(__float2half_rn(v));
    }
}

// ============================================================
// Kernel 4: 7x7 conv via mma.sync implicit GEMM, taps-outer / K=ci.
// fp16 2-pass: A (input) split hi/lo fp16 (~22 bits), B (weights) single fp16.
// Block tile: D[128 px (4h x 32w), 64 co]. A_ext built once; 49 taps read
// shifted rows. B double-buffered + register-prefetched. 64 MMA/warp/tap.
// ============================================================
#define ASTRIDE 144
#define AS_HI 0
#define AS_LO 54720                       // 380 * 144
#define BS_OFF(buf) (109440 + (buf) * 9216)
#define SMEM_TC 127872

__global__ void __launch_bounds__(256, 1) k_conv_mma(float* __restrict__ out,
                                                     const float* __restrict__ bias) {
    extern __shared__ unsigned char smem[];
    uint32_t sb = smem_u32(smem);
    int tid = threadIdx.x;
    int lane = tid & 31, wrp = tid >> 5;
    int mw = wrp & 3, nw = wrp >> 2;
    int b = blockIdx.z;
    int h0 = blockIdx.y * 4, w0 = blockIdx.x * 32;

    float acc[2][4][4];
#pragma unroll
    for (int mt = 0; mt < 2; ++mt)
#pragma unroll
        for (int nt = 0; nt < 4; ++nt)
#pragma unroll
            for (int r = 0; r < 4; ++r) acc[mt][nt][r] = 0.0f;

    // ldmatrix lane-offsets (fragment conventions validated in R5/R6)
    int tl = lane >> 3;
    int a_roff = (lane & 7) + (tl & 1) * 8;
    int a_coff = (tl >> 1) * 8;
    int b_roff = lane & 7;
    int b_coff = ((lane >> 3) & 1) * 8;

    uint32_t aBase[2];
#pragma unroll
    for (int mt = 0; mt < 2; ++mt) {
        int px = mw * 32 + mt * 16 + a_roff;
        int pr = px >> 5, pc = px & 31;
        aBase[mt] = sb + AS_HI + (uint32_t)(pr * 38 + pc) * ASTRIDE + (uint32_t)a_coff * 2;
    }
    uint32_t bBase = (uint32_t)(nw * 32 + b_roff) * ASTRIDE + (uint32_t)b_coff * 2;

    int b_co0 = tid >> 3, b_f4 = tid & 7;

    const float* inb = g_avg + (size_t)b * CC * HW;

    // ---- build A_ext once: 380 ext px x 64 ci, fp16 hi/lo ----
#pragma unroll 4
    for (int it = 0; it < 96; ++it) {
        int idx = tid + it * 256;                 // 0..24575 = 64 ci * 384 slots
        int ci = idx / 384, p = idx - ci * 384;
        if (p < 380) {
            int er = p / 38, ec = p - er * 38;
            int gh = h0 - 3 + er, gw = w0 - 3 + ec;
            float v = 0.0f;
            if (gh >= 0 && gh < HH && gw >= 0 && gw < WW) v = inb[(size_t)ci * HW + gh * WW + gw];
            __half xh = __float2half_rn(v);
            __half xl = __float2half_rn(v - __half2float(xh));
            *(unsigned short*)(smem + AS_HI + p * ASTRIDE + ci * 2) = __half_as_ushort(xh);
            *(unsigned short*)(smem + AS_LO + p * ASTRIDE + ci * 2) = __half_as_ushort(xl);
        }
    }
    // ---- stage B(tap 0) into buffer 0 ----
    {
        const float4* sh = (const float4*)(g_wt);
        float4* dh = (float4*)(smem + BS_OFF(0));
        dh[b_co0 * 9 + b_f4] = sh[tid];
        dh[(b_co0 + 32) * 9 + b_f4] = sh[tid + 256];
    }
    __syncthreads();

    int tapoff = 0;   // (ky*38 + kx) * ASTRIDE
    int kx = 0;
    for (int t = 0; t < 49; ++t) {
        int buf = t & 1;
        bool have_next = (t + 1 < 49);
        float4 vh0, vh1;
        if (have_next) {
            const float4* sh = (const float4*)(g_wt + (size_t)(t + 1) * (CC * CC));
            vh0 = sh[tid]; vh1 = sh[tid + 256];
        }

        uint32_t bhi = sb + BS_OFF(buf) + bBase;
#pragma unroll
        for (int j = 0; j < 4; ++j) {
            uint32_t Ah[2][4], Al[2][4];
#pragma unroll
            for (int mt = 0; mt < 2; ++mt) {
                uint32_t aa = aBase[mt] + (uint32_t)tapoff + (uint32_t)j * 32;
                LDMATRIX_X4(Ah[mt], aa);
                LDMATRIX_X4(Al[mt], aa + (AS_LO - AS_HI));
            }
#pragma unroll
            for (int nt = 0; nt < 4; ++nt) {
                uint32_t bo = (uint32_t)(nt * 8) * ASTRIDE + (uint32_t)j * 32;
                uint32_t Bf[2];
                LDMATRIX_X2(Bf, bhi + bo);
#pragma unroll
                for (int mt = 0; mt < 2; ++mt) {
                    MMA_F16(acc[mt][nt], Ah[mt], Bf);
                    MMA_F16(acc[mt][nt], Al[mt], Bf);
                }
            }
        }

        if (have_next) {
            int nb = buf ^ 1;
            float4* dh = (float4*)(smem + BS_OFF(nb));
            dh[b_co0 * 9 + b_f4] = vh0;
            dh[(b_co0 + 32) * 9 + b_f4] = vh1;
        }
        __syncthreads();

        // advance tap
        ++kx;
        if (kx == 7) { kx = 0; tapoff += 32 * ASTRIDE; }
        else tapoff += ASTRIDE;
    }

    // ---- epilogue ----
    int g = lane >> 2, tig = lane & 3;
    float* o = out + (size_t)b * CC * HW;
#pragma unroll
    for (int mt = 0; mt < 2; ++mt) {
        int r0 = mw * 32 + mt * 16 + g;
        int oh0 = h0 + (r0 >> 5), ow0 = w0 + (r0 & 31);
        int r1 = r0 + 8;
        int oh1 = h0 + (r1 >> 5), ow1 = w0 + (r1 & 31);
#pragma unroll
        for (int nt = 0; nt < 4; ++nt) {
            int co = nw * 32 + nt * 8 + tig * 2;
            float bv0 = __ldg(&bias[co]), bv1 = __ldg(&bias[co + 1]);
            o[(size_t)co * HW + oh0 * WW + ow0] = acc[mt][nt][0] + bv0;
            o[(size_t)(co + 1) * HW + oh0 * WW + ow0] = acc[mt][nt][1] + bv1;
            o[(size_t)co * HW + oh1 * WW + ow1] = acc[mt][nt][2] + bv0;
            o[(size_t)(co + 1) * HW + oh1 * WW + ow1] = acc[mt][nt][3] + bv1;
        }
    }
}

// ============================================================
extern "C" void kernel_launch(void* const* d_in, const int* in_sizes, int n_in,
                              void* d_out, int out_size) {
    const float* x   = (const float*)d_in[0];  // (10,64,100,352)
    const float* psm = (const float*)d_in[1];  // (10,2,100,352)
    // d_in[2] record_len: unused
    const float* pt  = (const float*)d_in[3];  // (2,5,5,4,4)
    const float* fw  = (const float*)d_in[4];  // (64,64,7,7)
    const float* fb  = (const float*)d_in[5];  // (64,)
    float* out = (float*)d_out;                // (2,64,100,352)

    cudaFuncSetAttribute(k_conv_mma, cudaFuncAttributeMaxDynamicSharedMemorySize, SMEM_TC);

    k_prepw<<<49, 256>>>(fw);
    k_confwarp<<<dim3(HH, NIMG), WW>>>(psm, pt);
    k_select<<<NIMG, 256>>>();
    k_warpacc<<<dim3(HH, 4, BB), WW>>>(x, pt);
    k_conv_mma<<<dim3(WW / 32, HH / 4, BB), 256, SMEM_TC>>>(out, fb);
}

// round 9
// speedup vs baseline: 4.0307x; 1.6083x over previous
#include <cuda_runtime.h>
#include <cuda_fp16.h>
#include <math.h>
#include <stdint.h>

#define NIMG 10
#define BB 2
#define LL 5
#define CC 64
#define HH 100
#define WW 352
#define HW 35200
#define KSEL 8800

// ---- scratch (static device globals; no allocation) ----
__device__ float g_confw[NIMG * HW];   // warped confidence (bit-exact vs XLA)
__device__ float g_thr[NIMG];          // per-sample K-th largest conf value
__device__ float g_avg[BB * CC * HW];  // (1/L) * sum_l sparse_l, per batch
// conv weights per tap, fp16: [t][co][ci], padded to 50 taps (tap 49 = 0)
__device__ unsigned short g_wt[50 * CC * CC];

// scale constants, computed in double then rounded to f32 (matches Python)
#define S01 ((float)(100.0 / 352.0))
#define S02 ((float)(2.0 / (2.0 * 0.4 * 352.0)))
#define S10 ((float)(352.0 / 100.0))
#define S12 ((float)(2.0 / (2.0 * 0.4 * 100.0)))
#define CXW ((float)(2.0 / 352.0))
#define CYH ((float)(2.0 / 100.0))

// ============================================================
// mma.sync / ldmatrix helpers (baseline PTX, sm_80+; OK on sm_103 plain)
// ============================================================
static __device__ __forceinline__ uint32_t smem_u32(const void* p) {
    uint32_t a;
    asm("{ .reg .u64 t; cvta.to.shared.u64 t, %1; cvt.u32.u64 %0, t; }" : "=r"(a) : "l"(p));
    return a;
}

#define LDMATRIX_X4(r, addr) \
    asm volatile("ldmatrix.sync.aligned.m8n8.x4.shared.b16 {%0,%1,%2,%3}, [%4];" \
        : "=r"((r)[0]), "=r"((r)[1]), "=r"((r)[2]), "=r"((r)[3]) : "r"(addr))

#define LDMATRIX_X2(r, addr) \
    asm volatile("ldmatrix.sync.aligned.m8n8.x2.shared.b16 {%0,%1}, [%2];" \
        : "=r"((r)[0]), "=r"((r)[1]) : "r"(addr))

#define MMA_F16(d, a, bfr) \
    asm volatile("mma.sync.aligned.m16n8k16.row.col.f32.f16.f16.f32 " \
        "{%0,%1,%2,%3}, {%4,%5,%6,%7}, {%8,%9}, {%0,%1,%2,%3};" \
        : "+f"((d)[0]), "+f"((d)[1]), "+f"((d)[2]), "+f"((d)[3]) \
        : "r"((a)[0]), "r"((a)[1]), "r"((a)[2]), "r"((a)[3]), "r"((bfr)[0]), "r"((bfr)[1]))

// ---- XLA f32 tanh (Eigen-style rational approx, uncontracted mul/add) ----
__device__ __forceinline__ float xla_tanh(float x) {
    float cx = fminf(fmaxf(x, -7.90531110763549805f), 7.90531110763549805f);
    float x2 = __fmul_rn(cx, cx);
    float p = -2.76076847742355e-16f;
    p = __fadd_rn(__fmul_rn(p, x2), 2.00018790482477e-13f);
    p = __fadd_rn(__fmul_rn(p, x2), -8.60467152213735e-11f);
    p = __fadd_rn(__fmul_rn(p, x2), 5.12229709037114e-08f);
    p = __fadd_rn(__fmul_rn(p, x2), 1.48572235717979e-05f);
    p = __fadd_rn(__fmul_rn(p, x2), 6.37261928875436e-04f);
    p = __fadd_rn(__fmul_rn(p, x2), 4.89352455891786e-03f);
    float num = __fmul_rn(cx, p);
    float q = 1.19825839466702e-06f;
    q = __fadd_rn(__fmul_rn(q, x2), 1.18534705686654e-04f);
    q = __fadd_rn(__fmul_rn(q, x2), 2.26843463243900e-03f);
    q = __fadd_rn(__fmul_rn(q, x2), 4.89352518554385e-03f);
    float r = __fdiv_rn(num, q);
    return (fabsf(x) < 0.0004f) ? x : r;
}
__device__ __forceinline__ float xla_sigmoid(float x) {
    return __fadd_rn(0.5f, __fmul_rn(0.5f, xla_tanh(__fmul_rn(0.5f, x))));
}

__device__ __forceinline__ void get_theta(const float* __restrict__ pt, int b, int l, float th[6]) {
    const float* p = pt + b * (LL * LL * 16) + l * 16;
    th[0] = p[0];
    th[1] = p[1] * S01;
    th[2] = p[3] * S02;
    th[3] = p[4] * S10;
    th[4] = p[5];
    th[5] = p[7] * S12;
}

// ============================================================
// Kernel 1: warp conf (strict XLA fp32 replication; feeds top-K mask)
// ============================================================
__global__ __launch_bounds__(WW) void k_confwarp(const float* __restrict__ psm,
                                                 const float* __restrict__ pt) {
    int h = blockIdx.x, n = blockIdx.y, w = threadIdx.x;
    int b = n / LL, l = n % LL;
    const float* p = pt + b * (LL * LL * 16) + l * 16;
    float th0 = p[0];
    float th1 = __fmul_rn(p[1], S01);
    float th2 = __fmul_rn(p[3], S02);
    float th3 = __fmul_rn(p[4], S10);
    float th4 = p[5];
    float th5 = __fmul_rn(p[7], S12);

    float gx = __fsub_rn(__fmul_rn(__fadd_rn((float)w, 0.5f), CXW), 1.0f);
    float gy = __fsub_rn(__fmul_rn(__fadd_rn((float)h, 0.5f), CYH), 1.0f);
    float src_x = __fadd_rn(__fadd_rn(__fmul_rn(th0, gx), __fmul_rn(th1, gy)), th2);
    float src_y = __fadd_rn(__fadd_rn(__fmul_rn(th3, gx), __fmul_rn(th4, gy)), th5);
    float px = __fsub_rn(__fmul_rn(__fadd_rn(src_x, 1.0f), 176.0f), 0.5f);
    float py = __fsub_rn(__fmul_rn(__fadd_rn(src_y, 1.0f), 50.0f), 0.5f);
    float x0 = floorf(px), y0 = floorf(py);
    float wx1 = __fsub_rn(px, x0), wx0 = __fsub_rn(1.0f, wx1);
    float wy1 = __fsub_rn(py, y0), wy0 = __fsub_rn(1.0f, wy1);

    const float* base = psm + (size_t)n * 2 * HW;
    float acc = 0.0f;
#pragma unroll
    for (int dy = 0; dy < 2; ++dy) {
#pragma unroll
        for (int dx = 0; dx < 2; ++dx) {
            float yy = dy ? __fadd_rn(y0, 1.0f) : y0;
            float xx = dx ? __fadd_rn(x0, 1.0f) : x0;
            if (yy >= 0.0f && yy <= (float)(HH - 1) && xx >= 0.0f && xx <= (float)(WW - 1)) {
                int yi = (int)yy, xi = (int)xx;
                float m = fmaxf(base[yi * WW + xi], base[HW + yi * WW + xi]);
                float s = xla_sigmoid(m);
                float wgt = __fmul_rn(dy ? wy1 : wy0, dx ? wx1 : wx0);
                acc = __fadd_rn(acc, __fmul_rn(s, wgt));
            }
        }
    }
    g_confw[n * HW + h * WW + w] = acc;
}

// ============================================================
// Kernel 2: exact K-th largest via 4x8-bit MSB radix select. 1024 threads
// per block for latency hiding (only 10 blocks on the grid).
// ============================================================
__global__ __launch_bounds__(1024) void k_select() {
    int n = blockIdx.x;
    const float* v = g_confw + n * HW;
    __shared__ unsigned int hist[256];
    __shared__ unsigned int s_prefix, s_krem;
    if (threadIdx.x == 0) { s_prefix = 0u; s_krem = KSEL; }
    __syncthreads();
    for (int pass = 0; pass < 4; ++pass) {
        int shift = 24 - pass * 8;
        unsigned int pmask = (pass == 0) ? 0u : (0xFFFFFFFFu << (shift + 8));
        for (int i = threadIdx.x; i < 256; i += blockDim.x) hist[i] = 0u;
        __syncthreads();
        unsigned int prefix = s_prefix;
        for (int i = threadIdx.x; i < HW; i += blockDim.x) {
            unsigned int key = __float_as_uint(v[i]);
            if ((key & pmask) == prefix) atomicAdd(&hist[(key >> shift) & 255u], 1u);
        }
        __syncthreads();
        if (threadIdx.x == 0) {
            unsigned int krem = s_krem, c = 0u; int sel = 0;
            for (int bin = 255; bin >= 0; --bin) {
                c += hist[bin];
                if (c >= krem) { sel = bin; krem -= (c - hist[bin]); break; }
            }
            s_prefix = prefix | ((unsigned int)sel << shift);
            s_krem = krem;
        }
        __syncthreads();
    }
    if (threadIdx.x == 0) g_thr[n] = __uint_as_float(s_prefix);
}

// ============================================================
// Kernel 3: warp x + mask + (1/L)-accumulate over l. grid (H, 4, B), block W
// ============================================================
__global__ __launch_bounds__(WW) void k_warpacc(const float* __restrict__ x,
                                                const float* __restrict__ pt) {
    int h = blockIdx.x, cg = blockIdx.y, b = blockIdx.z, w = threadIdx.x;
    float acc[16];
#pragma unroll
    for (int i = 0; i < 16; ++i) acc[i] = 0.0f;
    float gx = (w + 0.5f) * (2.0f / WW) - 1.0f;
    float gy = (h + 0.5f) * (2.0f / HH) - 1.0f;
    for (int l = 0; l < LL; ++l) {
        int n = b * LL + l;
        if (l != 0 && g_confw[n * HW + h * WW + w] < g_thr[n]) continue;
        float th[6];
        get_theta(pt, b, l, th);
        float px = (th[0] * gx + th[1] * gy + th[2] + 1.0f) * (WW * 0.5f) - 0.5f;
        float py = (th[3] * gx + th[4] * gy + th[5] + 1.0f) * (HH * 0.5f) - 0.5f;
        float x0 = floorf(px), y0 = floorf(py);
        float wx1 = px - x0, wx0 = 1.0f - wx1;
        float wy1 = py - y0, wy0 = 1.0f - wy1;
        bool vx0 = (x0 >= 0.0f) && (x0 <= (float)(WW - 1));
        bool vx1 = (x0 + 1.0f >= 0.0f) && (x0 + 1.0f <= (float)(WW - 1));
        bool vy0 = (y0 >= 0.0f) && (y0 <= (float)(HH - 1));
        bool vy1 = (y0 + 1.0f >= 0.0f) && (y0 + 1.0f <= (float)(HH - 1));
        int x0i = (int)fminf(fmaxf(x0, 0.0f), (float)(WW - 1));
        int x1i = (int)fminf(fmaxf(x0 + 1.0f, 0.0f), (float)(WW - 1));
        int y0i = (int)fminf(fmaxf(y0, 0.0f), (float)(HH - 1));
        int y1i = (int)fminf(fmaxf(y0 + 1.0f, 0.0f), (float)(HH - 1));
        float m00 = (vy0 && vx0) ? wy0 * wx0 * 0.2f : 0.0f;
        float m01 = (vy0 && vx1) ? wy0 * wx1 * 0.2f : 0.0f;
        float m10 = (vy1 && vx0) ? wy1 * wx0 * 0.2f : 0.0f;
        float m11 = (vy1 && vx1) ? wy1 * wx1 * 0.2f : 0.0f;
        int i00 = y0i * WW + x0i, i01 = y0i * WW + x1i;
        int i10 = y1i * WW + x0i, i11 = y1i * WW + x1i;
        const float* xb = x + (size_t)(n * CC + cg * 16) * HW;
#pragma unroll
        for (int c = 0; c < 16; ++c) {
            const float* xc = xb + c * HW;
            acc[c] += xc[i00] * m00 + xc[i01] * m01 + xc[i10] * m10 + xc[i11] * m11;
        }
    }
    int outbase = ((b * CC + cg * 16) * HH + h) * WW + w;
#pragma unroll
    for (int c = 0; c < 16; ++c) g_avg[outbase + c * HW] = acc[c];
}

// ============================================================
// Kernel 3b: weights -> fp16 per tap: g_wt[t][co][ci]. grid 50 (tap 49 = 0).
// ============================================================
__global__ __launch_bounds__(256) void k_prepw(const float* __restrict__ fw) {
    int t = blockIdx.x;
    for (int e = threadIdx.x; e < CC * CC; e += 256) {
        int co = e >> 6, ci = e & 63;
        float v = (t < 49) ? fw[(size_t)(co * CC + ci) * 49 + t] : 0.0f;
        g_wt[(size_t)t * (CC * CC) + e] = __half_as_ushort(__float2half_rn(v));
    }
}

// ============================================================
// Kernel 4: 7x7 conv via mma.sync implicit GEMM, taps-outer / K=ci.
// Single-pass fp16 (input + weights fp16; fp32 accumulate).
// Block tile: D[128 px (4h x 32w), 64 co]. A_ext (380 x 64ci fp16) built
// once; 50 taps (1 zero pad) in 25 two-tap barrier stages, B double-buffered
// + register-prefetched. 32 MMA/warp/tap. 2 blocks/SM (91.6KB smem).
// ============================================================
#define ASTRIDE 144
#define AS_SZ 54720                       // 380 * 144
#define BS_OFF(buf) (AS_SZ + (buf) * 18432)
#define SMEM_TC 91584

__global__ void __launch_bounds__(256, 2) k_conv_mma(float* __restrict__ out,
                                                     const float* __restrict__ bias) {
    extern __shared__ unsigned char smem[];
    uint32_t sb = smem_u32(smem);
    int tid = threadIdx.x;
    int lane = tid & 31, wrp = tid >> 5;
    int mw = wrp & 3, nw = wrp >> 2;
    int b = blockIdx.z;
    int h0 = blockIdx.y * 4, w0 = blockIdx.x * 32;

    float acc[2][4][4];
#pragma unroll
    for (int mt = 0; mt < 2; ++mt)
#pragma unroll
        for (int nt = 0; nt < 4; ++nt)
#pragma unroll
            for (int r = 0; r < 4; ++r) acc[mt][nt][r] = 0.0f;

    // ldmatrix lane-offsets (fragment conventions validated R5-R7)
    int tl = lane >> 3;
    int a_roff = (lane & 7) + (tl & 1) * 8;
    int a_coff = (tl >> 1) * 8;
    int b_roff = lane & 7;
    int b_coff = ((lane >> 3) & 1) * 8;

    uint32_t aBase[2];
#pragma unroll
    for (int mt = 0; mt < 2; ++mt) {
        int px = mw * 32 + mt * 16 + a_roff;
        int pr = px >> 5, pc = px & 31;
        aBase[mt] = sb + (uint32_t)(pr * 38 + pc) * ASTRIDE + (uint32_t)a_coff * 2;
    }
    uint32_t bBase = (uint32_t)(nw * 32 + b_roff) * ASTRIDE + (uint32_t)b_coff * 2;

    int b_co0 = tid >> 3, b_f4 = tid & 7;

    const float* inb = g_avg + (size_t)b * CC * HW;

    // ---- build A_ext once: 380 ext px x 64 ci, fp16 ----
#pragma unroll 4
    for (int it = 0; it < 96; ++it) {
        int idx = tid + it * 256;                 // 0..24575 = 64 ci * 384 slots
        int ci = idx / 384, p = idx - ci * 384;
        if (p < 380) {
            int er = p / 38, ec = p - er * 38;
            int gh = h0 - 3 + er, gw = w0 - 3 + ec;
            float v = 0.0f;
            if (gh >= 0 && gh < HH && gw >= 0 && gw < WW) v = inb[(size_t)ci * HW + gh * WW + gw];
            *(unsigned short*)(smem + p * ASTRIDE + ci * 2) =
                __half_as_ushort(__float2half_rn(v));
        }
    }
    // ---- stage B taps 0,1 into buffer 0 ----
    {
        const float4* s0 = (const float4*)(g_wt);
        const float4* s1 = (const float4*)(g_wt + (size_t)1 * (CC * CC));
        float4* d0 = (float4*)(smem + BS_OFF(0));
        float4* d1 = (float4*)(smem + BS_OFF(0) + 9216);
        d0[b_co0 * 9 + b_f4] = s0[tid];
        d0[(b_co0 + 32) * 9 + b_f4] = s0[tid + 256];
        d1[b_co0 * 9 + b_f4] = s1[tid];
        d1[(b_co0 + 32) * 9 + b_f4] = s1[tid + 256];
    }
    __syncthreads();

    for (int s = 0; s < 25; ++s) {
        int buf = s & 1;
        bool have_next = (s + 1 < 25);
        float4 v00, v01, v10, v11;
        if (have_next) {
            const float4* s0 = (const float4*)(g_wt + (size_t)(2 * s + 2) * (CC * CC));
            const float4* s1 = (const float4*)(g_wt + (size_t)(2 * s + 3) * (CC * CC));
            v00 = s0[tid]; v01 = s0[tid + 256];
            v10 = s1[tid]; v11 = s1[tid + 256];
        }

        // two taps of this stage
#pragma unroll
        for (int ti = 0; ti < 2; ++ti) {
            int t = 2 * s + ti;
            int toff = (t < 49) ? ((t / 7) * 38 + (t % 7)) * ASTRIDE : 0;  // pad tap: w=0
            uint32_t bptr = sb + BS_OFF(buf) + (uint32_t)ti * 9216 + bBase;
#pragma unroll
            for (int j = 0; j < 4; ++j) {
                uint32_t Ah[2][4];
#pragma unroll
                for (int mt = 0; mt < 2; ++mt)
                    LDMATRIX_X4(Ah[mt], aBase[mt] + (uint32_t)toff + (uint32_t)j * 32);
#pragma unroll
                for (int nt = 0; nt < 4; ++nt) {
                    uint32_t Bf[2];
                    LDMATRIX_X2(Bf, bptr + (uint32_t)(nt * 8) * ASTRIDE + (uint32_t)j * 32);
#pragma unroll
                    for (int mt = 0; mt < 2; ++mt)
                        MMA_F16(acc[mt][nt], Ah[mt], Bf);
                }
            }
        }

        if (have_next) {
            int nb = buf ^ 1;
            float4* d0 = (float4*)(smem + BS_OFF(nb));
            float4* d1 = (float4*)(smem + BS_OFF(nb) + 9216);
            d0[b_co0 * 9 + b_f4] = v00;
            d0[(b_co0 + 32) * 9 + b_f4] = v01;
            d1[b_co0 * 9 + b_f4] = v10;
            d1[(b_co0 + 32) * 9 + b_f4] = v11;
        }
        __syncthreads();
    }

    // ---- epilogue ----
    int g = lane >> 2, tig = lane & 3;
    float* o = out + (size_t)b * CC * HW;
#pragma unroll
    for (int mt = 0; mt < 2; ++mt) {
        int r0 = mw * 32 + mt * 16 + g;
        int oh0 = h0 + (r0 >> 5), ow0 = w0 + (r0 & 31);
        int r1 = r0 + 8;
        int oh1 = h0 + (r1 >> 5), ow1 = w0 + (r1 & 31);
#pragma unroll
        for (int nt = 0; nt < 4; ++nt) {
            int co = nw * 32 + nt * 8 + tig * 2;
            float bv0 = __ldg(&bias[co]), bv1 = __ldg(&bias[co + 1]);
            o[(size_t)co * HW + oh0 * WW + ow0] = acc[mt][nt][0] + bv0;
            o[(size_t)(co + 1) * HW + oh0 * WW + ow0] = acc[mt][nt][1] + bv1;
            o[(size_t)co * HW + oh1 * WW + ow1] = acc[mt][nt][2] + bv0;
            o[(size_t)(co + 1) * HW + oh1 * WW + ow1] = acc[mt][nt][3] + bv1;
        }
    }
}

// ============================================================
extern "C" void kernel_launch(void* const* d_in, const int* in_sizes, int n_in,
                              void* d_out, int out_size) {
    const float* x   = (const float*)d_in[0];  // (10,64,100,352)
    const float* psm = (const float*)d_in[1];  // (10,2,100,352)
    // d_in[2] record_len: unused
    const float* pt  = (const float*)d_in[3];  // (2,5,5,4,4)
    const float* fw  = (const float*)d_in[4];  // (64,64,7,7)
    const float* fb  = (const float*)d_in[5];  // (64,)
    float* out = (float*)d_out;                // (2,64,100,352)

    cudaFuncSetAttribute(k_conv_mma, cudaFuncAttributeMaxDynamicSharedMemorySize, SMEM_TC);

    k_prepw<<<50, 256>>>(fw);
    k_confwarp<<<dim3(HH, NIMG), WW>>>(psm, pt);
    k_select<<<NIMG, 1024>>>();
    k_warpacc<<<dim3(HH, 4, BB), WW>>>(x, pt);
    k_conv_mma<<<dim3(WW / 32, HH / 4, BB), 256, SMEM_TC>>>(out, fb);
}